// round 1
// baseline (speedup 1.0000x reference)
#include <cuda_runtime.h>
#include <math.h>

// Problem constants
#define BATCH 4
#define SEQ   2048
#define EMB   1024
#define HEADS 16
#define HDIM  64
#define MROWS (BATCH*SEQ)   // 8192

// Scratch (device globals: no allocation allowed)
__device__ float g_q [MROWS*EMB];
__device__ float g_k [MROWS*EMB];
__device__ float g_v [MROWS*EMB];
__device__ float g_ao[MROWS*EMB];

// ---------------------------------------------------------------------------
// SGEMM: C[m,n] = sum_k A[m,k] * W[n,k]  (+ bias[n])
// A: [M,K] row-major, W: [N,K] row-major (i.e. C = A @ W^T), C: [M,N] row-major
// 128x128 block tile, BK=8, 256 threads, 8x8 per thread (strided register tile)
// ---------------------------------------------------------------------------
template<bool HAS_BIAS>
__global__ __launch_bounds__(256)
void sgemm_nt(const float* __restrict__ A,
              const float* __restrict__ W,
              const float* __restrict__ bias,
              float* __restrict__ C,
              int M, int Nn, int K)
{
    const int BM = 128, BN = 128, BK = 8;
    __shared__ float As[8][128];
    __shared__ float Bs[8][128];

    const int tid = threadIdx.x;
    const int tx = tid & 15;      // col group
    const int ty = tid >> 4;      // row group
    const int bx = blockIdx.x;    // n tile
    const int by = blockIdx.y;    // m tile

    // Loader mapping: each thread loads one float4 of A and one of W per BK step
    const int lr = tid >> 1;            // 0..127 (row within tile)
    const int lk = (tid & 1) * 4;       // 0 or 4 (k offset)

    const float* Ap = A + (size_t)(by * BM + lr) * K + lk;
    const float* Wp = W + (size_t)(bx * BN + lr) * K + lk;

    float acc[8][8];
    #pragma unroll
    for (int i = 0; i < 8; i++)
        #pragma unroll
        for (int j = 0; j < 8; j++)
            acc[i][j] = 0.f;

    for (int k0 = 0; k0 < K; k0 += BK) {
        float4 a = *(const float4*)(Ap + k0);
        float4 w = *(const float4*)(Wp + k0);
        As[lk + 0][lr] = a.x; As[lk + 1][lr] = a.y;
        As[lk + 2][lr] = a.z; As[lk + 3][lr] = a.w;
        Bs[lk + 0][lr] = w.x; Bs[lk + 1][lr] = w.y;
        Bs[lk + 2][lr] = w.z; Bs[lk + 3][lr] = w.w;
        __syncthreads();

        #pragma unroll
        for (int kk = 0; kk < BK; kk++) {
            float ra[8], rb[8];
            #pragma unroll
            for (int i = 0; i < 8; i++) ra[i] = As[kk][i * 16 + ty];
            #pragma unroll
            for (int j = 0; j < 8; j++) rb[j] = Bs[kk][j * 16 + tx];
            #pragma unroll
            for (int i = 0; i < 8; i++)
                #pragma unroll
                for (int j = 0; j < 8; j++)
                    acc[i][j] = fmaf(ra[i], rb[j], acc[i][j]);
        }
        __syncthreads();
    }

    #pragma unroll
    for (int i = 0; i < 8; i++) {
        const int row = by * BM + i * 16 + ty;
        #pragma unroll
        for (int j = 0; j < 8; j++) {
            const int col = bx * BN + j * 16 + tx;
            float v = acc[i][j];
            if (HAS_BIAS) v += bias[col];
            C[(size_t)row * Nn + col] = v;
        }
    }
}

// ---------------------------------------------------------------------------
// Flash attention, fp32, online softmax.
// q/k/v layout: row (b*SEQ + n), col (h*HDIM + dh)  (row stride EMB)
// One block = 64 q-rows for one (b,h). 64-wide KV tiles. 256 threads.
// Thread (ty=tid/16, tx=tid%16) owns q rows {i*16+ty}, cols {j*16+tx}, i,j<4.
// ---------------------------------------------------------------------------
#define FA_PITCH 65
#define FA_SMEM  (3 * 64 * FA_PITCH * 4)   // 49920 bytes

__global__ __launch_bounds__(256)
void flash_fp32(const float* __restrict__ Q,
                const float* __restrict__ K,
                const float* __restrict__ V,
                float* __restrict__ Out)
{
    extern __shared__ float sm[];
    float* Qt  = sm;                    // [HDIM][PITCH]  transposed: Qt[d][q]
    float* KVs = sm + 64 * FA_PITCH;    // Kt[d][kv] during S, Vs[kv][d] during PV
    float* Ps  = sm + 2 * 64 * FA_PITCH;// [q][PITCH]

    const int tid = threadIdx.x;
    const int tx = tid & 15;
    const int ty = tid >> 4;
    const int q0 = blockIdx.x * 64;
    const int h  = blockIdx.y;
    const int b  = blockIdx.z;

    const float* qbase = Q + ((size_t)(b * SEQ) + q0) * EMB + h * HDIM;
    const float* kbase = K + (size_t)(b * SEQ) * EMB + h * HDIM;
    const float* vbase = V + (size_t)(b * SEQ) * EMB + h * HDIM;

    // Load Q tile transposed + pre-scaled by 1/sqrt(Dh) = 0.125 (exact)
    #pragma unroll
    for (int t = 0; t < 4; t++) {
        int idx = tid + t * 256;
        int r = idx >> 4;             // q row 0..63
        int c = (idx & 15) * 4;       // dh col
        float4 qv = *(const float4*)(qbase + (size_t)r * EMB + c);
        Qt[(c + 0) * FA_PITCH + r] = qv.x * 0.125f;
        Qt[(c + 1) * FA_PITCH + r] = qv.y * 0.125f;
        Qt[(c + 2) * FA_PITCH + r] = qv.z * 0.125f;
        Qt[(c + 3) * FA_PITCH + r] = qv.w * 0.125f;
    }

    float m_i[4], l_i[4], acc[4][4];
    #pragma unroll
    for (int i = 0; i < 4; i++) {
        m_i[i] = -INFINITY;
        l_i[i] = 0.f;
        #pragma unroll
        for (int j = 0; j < 4; j++) acc[i][j] = 0.f;
    }
    __syncthreads();

    for (int kv0 = 0; kv0 < SEQ; kv0 += 64) {
        // ---- load K tile transposed: Kt[d][kv]
        #pragma unroll
        for (int t = 0; t < 4; t++) {
            int idx = tid + t * 256;
            int r = idx >> 4;
            int c = (idx & 15) * 4;
            float4 kv = *(const float4*)(kbase + (size_t)(kv0 + r) * EMB + c);
            KVs[(c + 0) * FA_PITCH + r] = kv.x;
            KVs[(c + 1) * FA_PITCH + r] = kv.y;
            KVs[(c + 2) * FA_PITCH + r] = kv.z;
            KVs[(c + 3) * FA_PITCH + r] = kv.w;
        }
        __syncthreads();

        // ---- S = Q @ K^T (scaled)
        float s[4][4];
        #pragma unroll
        for (int i = 0; i < 4; i++)
            #pragma unroll
            for (int j = 0; j < 4; j++) s[i][j] = 0.f;

        #pragma unroll 8
        for (int d = 0; d < HDIM; d++) {
            float ra[4], rb[4];
            #pragma unroll
            for (int i = 0; i < 4; i++) ra[i] = Qt[d * FA_PITCH + i * 16 + ty];
            #pragma unroll
            for (int j = 0; j < 4; j++) rb[j] = KVs[d * FA_PITCH + j * 16 + tx];
            #pragma unroll
            for (int i = 0; i < 4; i++)
                #pragma unroll
                for (int j = 0; j < 4; j++)
                    s[i][j] = fmaf(ra[i], rb[j], s[i][j]);
        }

        // ---- online softmax update (row reductions over 16 tx lanes)
        #pragma unroll
        for (int i = 0; i < 4; i++) {
            float mt = s[i][0];
            #pragma unroll
            for (int j = 1; j < 4; j++) mt = fmaxf(mt, s[i][j]);
            #pragma unroll
            for (int off = 8; off > 0; off >>= 1)
                mt = fmaxf(mt, __shfl_xor_sync(0xffffffffu, mt, off, 16));

            float mn = fmaxf(m_i[i], mt);
            float alpha = __expf(m_i[i] - mn);
            m_i[i] = mn;

            float ls = 0.f;
            #pragma unroll
            for (int j = 0; j < 4; j++) {
                s[i][j] = __expf(s[i][j] - mn);
                ls += s[i][j];
            }
            #pragma unroll
            for (int off = 8; off > 0; off >>= 1)
                ls += __shfl_xor_sync(0xffffffffu, ls, off, 16);
            l_i[i] = l_i[i] * alpha + ls;

            #pragma unroll
            for (int j = 0; j < 4; j++) {
                acc[i][j] *= alpha;
                Ps[(i * 16 + ty) * FA_PITCH + j * 16 + tx] = s[i][j];
            }
        }
        __syncthreads();   // Ps visible; Kt reads finished

        // ---- load V tile row-major: Vs[kv][d]
        #pragma unroll
        for (int t = 0; t < 4; t++) {
            int idx = tid + t * 256;
            int r = idx >> 4;
            int c = (idx & 15) * 4;
            float4 vv = *(const float4*)(vbase + (size_t)(kv0 + r) * EMB + c);
            KVs[r * FA_PITCH + c + 0] = vv.x;
            KVs[r * FA_PITCH + c + 1] = vv.y;
            KVs[r * FA_PITCH + c + 2] = vv.z;
            KVs[r * FA_PITCH + c + 3] = vv.w;
        }
        __syncthreads();

        // ---- O += P @ V
        #pragma unroll 8
        for (int kv = 0; kv < 64; kv++) {
            float rp[4], rv[4];
            #pragma unroll
            for (int i = 0; i < 4; i++) rp[i] = Ps[(i * 16 + ty) * FA_PITCH + kv];
            #pragma unroll
            for (int j = 0; j < 4; j++) rv[j] = KVs[kv * FA_PITCH + j * 16 + tx];
            #pragma unroll
            for (int i = 0; i < 4; i++)
                #pragma unroll
                for (int j = 0; j < 4; j++)
                    acc[i][j] = fmaf(rp[i], rv[j], acc[i][j]);
        }
        __syncthreads();   // KVs/Ps free for next tile
    }

    // ---- epilogue: normalize and write [b,n,h,dh]
    #pragma unroll
    for (int i = 0; i < 4; i++) {
        const float inv = 1.0f / l_i[i];
        const int q = q0 + i * 16 + ty;
        #pragma unroll
        for (int j = 0; j < 4; j++) {
            Out[((size_t)(b * SEQ) + q) * EMB + h * HDIM + j * 16 + tx] =
                acc[i][j] * inv;
        }
    }
}

// ---------------------------------------------------------------------------
extern "C" void kernel_launch(void* const* d_in, const int* in_sizes, int n_in,
                              void* d_out, int out_size)
{
    const float* x  = (const float*)d_in[0];
    const float* Wq = (const float*)d_in[1];
    const float* bq = (const float*)d_in[2];
    const float* Wk = (const float*)d_in[3];
    const float* bk = (const float*)d_in[4];
    const float* Wv = (const float*)d_in[5];
    const float* bv = (const float*)d_in[6];
    const float* Wo = (const float*)d_in[7];
    float* out = (float*)d_out;

    float *qp, *kp, *vp, *aop;
    cudaGetSymbolAddress((void**)&qp,  g_q);
    cudaGetSymbolAddress((void**)&kp,  g_k);
    cudaGetSymbolAddress((void**)&vp,  g_v);
    cudaGetSymbolAddress((void**)&aop, g_ao);

    cudaFuncSetAttribute(flash_fp32,
                         cudaFuncAttributeMaxDynamicSharedMemorySize, FA_SMEM);

    dim3 gg(EMB / 128, MROWS / 128);   // (8, 64)

    sgemm_nt<true><<<gg, 256>>>(x, Wq, bq, qp, MROWS, EMB, EMB);
    sgemm_nt<true><<<gg, 256>>>(x, Wk, bk, kp, MROWS, EMB, EMB);
    sgemm_nt<true><<<gg, 256>>>(x, Wv, bv, vp, MROWS, EMB, EMB);

    dim3 fg(SEQ / 64, HEADS, BATCH);   // (32, 16, 4)
    flash_fp32<<<fg, 256, FA_SMEM>>>(qp, kp, vp, aop);

    sgemm_nt<false><<<gg, 256>>>(aop, Wo, nullptr, out, MROWS, EMB, EMB);
}

// round 6
// speedup vs baseline: 1.3642x; 1.3642x over previous
#include <cuda_runtime.h>
#include <cuda_bf16.h>
#include <cuda_pipeline.h>
#include <mma.h>
#include <math.h>
#include <stdint.h>

using namespace nvcuda;

// Problem constants
#define BATCH 4
#define SEQ   2048
#define EMB   1024
#define HEADS 16
#define HDIM  64
#define MROWS (BATCH*SEQ)   // 8192

// ---------------------------------------------------------------------------
// Scratch (device globals: no allocation allowed).
// attn-out hi/lo reuse x hi/lo (dead after third QKV GEMM; stream-ordered).
// ---------------------------------------------------------------------------
__device__ float g_q [MROWS*EMB];
__device__ float g_k [MROWS*EMB];
__device__ float g_v [MROWS*EMB];
__device__ float g_ao[MROWS*EMB];

__device__ __nv_bfloat16 g_xh [MROWS*EMB];
__device__ __nv_bfloat16 g_xl [MROWS*EMB];
__device__ __nv_bfloat16 g_wh [4*EMB*EMB];
__device__ __nv_bfloat16 g_wl [4*EMB*EMB];

// ---------------------------------------------------------------------------
// Split fp32 -> (bf16 hi, bf16 lo).  n4 = n/4 float4s.
// ---------------------------------------------------------------------------
__global__ __launch_bounds__(256)
void split_kernel(const float* __restrict__ src,
                  __nv_bfloat16* __restrict__ hi,
                  __nv_bfloat16* __restrict__ lo, int n4)
{
    int i = blockIdx.x * blockDim.x + threadIdx.x;
    if (i >= n4) return;
    float4 v = ((const float4*)src)[i];
    __nv_bfloat16 h0 = __float2bfloat16(v.x);
    __nv_bfloat16 h1 = __float2bfloat16(v.y);
    __nv_bfloat16 h2 = __float2bfloat16(v.z);
    __nv_bfloat16 h3 = __float2bfloat16(v.w);
    __nv_bfloat16 l0 = __float2bfloat16(v.x - __bfloat162float(h0));
    __nv_bfloat16 l1 = __float2bfloat16(v.y - __bfloat162float(h1));
    __nv_bfloat16 l2 = __float2bfloat16(v.z - __bfloat162float(h2));
    __nv_bfloat16 l3 = __float2bfloat16(v.w - __bfloat162float(h3));
    __nv_bfloat162* hp = (__nv_bfloat162*)hi;
    __nv_bfloat162* lp = (__nv_bfloat162*)lo;
    __nv_bfloat162 a; a.x = h0; a.y = h1;
    __nv_bfloat162 b; b.x = h2; b.y = h3;
    __nv_bfloat162 c; c.x = l0; c.y = l1;
    __nv_bfloat162 d; d.x = l2; d.y = l3;
    hp[i*2+0] = a; hp[i*2+1] = b;
    lp[i*2+0] = c; lp[i*2+1] = d;
}

// ---------------------------------------------------------------------------
// WMMA split-bf16 GEMM: C[m,n] = sum_k A[m,k]*W[n,k] (+bias[n]), fp32 out.
// CTA 128x128, BK=32, 8 warps (2m x 4n), warp tile 64x32 (4x2 wmma 16x16x16).
// 3 passes per k-step: ah*bh + ah*bl + al*bh into one fp32 accumulator.
// No inline PTX: nvcuda::wmma + cuda_pipeline intrinsics only.
// ---------------------------------------------------------------------------
#define BK        32
#define NCHUNKS   (EMB/BK)            // 32
#define PITCH_E   48                  // smem row pitch in bf16 elems (96 B, 32B-aligned rows)
#define TILE_SB   (128*PITCH_E*2)     // 12288 B per operand tile
#define STAGE_SB  (4*TILE_SB)         // Ah Al Bh Bl = 49152 B
#define GEMM_SMEM (2*STAGE_SB)        // 98304 B (also >= 128*132*4 staging)

__global__ __launch_bounds__(256)
void gemm_wmma(const __nv_bfloat16* __restrict__ Ah, const __nv_bfloat16* __restrict__ Al,
               const __nv_bfloat16* __restrict__ Bh, const __nv_bfloat16* __restrict__ Bl,
               const float* __restrict__ bias, float* __restrict__ C, int Nn)
{
    extern __shared__ char smc[];
    const int tid  = threadIdx.x;
    const int wid  = tid >> 5;
    const int warp_m = wid >> 2;       // 0..1
    const int warp_n = wid & 3;        // 0..3
    const int bx = blockIdx.x;         // n tile
    const int by = blockIdx.y;         // m tile

    // Global byte bases (row stride = 1024 bf16 = 2048 B)
    const char* ahg = (const char*)Ah + (size_t)(by*128) * 2048;
    const char* alg = (const char*)Al + (size_t)(by*128) * 2048;
    const char* bhg = (const char*)Bh + (size_t)(bx*128) * 2048;
    const char* blg = (const char*)Bl + (size_t)(bx*128) * 2048;

    // Loader: per operand tile 128 rows x 64 B = 512 x 16B chunks; 2/thread/tile
    int lrow[2], lcb[2];
    #pragma unroll
    for (int i = 0; i < 2; i++) {
        int idx = tid + i * 256;
        lrow[i] = idx >> 2;            // 0..127
        lcb[i]  = (idx & 3) * 16;      // 0,16,32,48
    }

    auto load_chunk = [&](int c, int stage) {
        char* st = smc + stage * STAGE_SB;
        const int ko = c * 64;         // 32 bf16 = 64 B along K
        #pragma unroll
        for (int i = 0; i < 2; i++) {
            const int    so = lrow[i] * (PITCH_E*2) + lcb[i];
            const size_t go = (size_t)lrow[i] * 2048 + ko + lcb[i];
            __pipeline_memcpy_async(st + 0*TILE_SB + so, ahg + go, 16);
            __pipeline_memcpy_async(st + 1*TILE_SB + so, alg + go, 16);
            __pipeline_memcpy_async(st + 2*TILE_SB + so, bhg + go, 16);
            __pipeline_memcpy_async(st + 3*TILE_SB + so, blg + go, 16);
        }
        __pipeline_commit();
    };

    wmma::fragment<wmma::accumulator, 16, 16, 16, float> acc[4][2];
    #pragma unroll
    for (int mt = 0; mt < 4; mt++)
        #pragma unroll
        for (int nt = 0; nt < 2; nt++)
            wmma::fill_fragment(acc[mt][nt], 0.0f);

    load_chunk(0, 0);

    for (int c = 0; c < NCHUNKS; c++) {
        if (c + 1 < NCHUNKS) {
            load_chunk(c + 1, (c + 1) & 1);
            __pipeline_wait_prior(1);
        } else {
            __pipeline_wait_prior(0);
        }
        __syncthreads();

        char* st = smc + (c & 1) * STAGE_SB;
        const __nv_bfloat16* ahs = (const __nv_bfloat16*)(st + 0*TILE_SB);
        const __nv_bfloat16* als = (const __nv_bfloat16*)(st + 1*TILE_SB);
        const __nv_bfloat16* bhs = (const __nv_bfloat16*)(st + 2*TILE_SB);
        const __nv_bfloat16* bls = (const __nv_bfloat16*)(st + 3*TILE_SB);

        #pragma unroll
        for (int ks = 0; ks < 2; ks++) {
            const int ke = ks * 16;    // elem offset along K

            wmma::fragment<wmma::matrix_a, 16, 16, 16, __nv_bfloat16, wmma::row_major> fah[4], fal[4];
            #pragma unroll
            for (int mt = 0; mt < 4; mt++) {
                const int ro = (warp_m*64 + mt*16) * PITCH_E + ke;
                wmma::load_matrix_sync(fah[mt], ahs + ro, PITCH_E);
                wmma::load_matrix_sync(fal[mt], als + ro, PITCH_E);
            }
            // W rows are output cols: element (k,n) of B = W[n][k] at n*PITCH+k -> col_major
            wmma::fragment<wmma::matrix_b, 16, 16, 16, __nv_bfloat16, wmma::col_major> fbh[2], fbl[2];
            #pragma unroll
            for (int nt = 0; nt < 2; nt++) {
                const int ro = (warp_n*32 + nt*16) * PITCH_E + ke;
                wmma::load_matrix_sync(fbh[nt], bhs + ro, PITCH_E);
                wmma::load_matrix_sync(fbl[nt], bls + ro, PITCH_E);
            }

            #pragma unroll
            for (int mt = 0; mt < 4; mt++)
                #pragma unroll
                for (int nt = 0; nt < 2; nt++) {
                    wmma::mma_sync(acc[mt][nt], fah[mt], fbh[nt], acc[mt][nt]);
                    wmma::mma_sync(acc[mt][nt], fah[mt], fbl[nt], acc[mt][nt]);
                    wmma::mma_sync(acc[mt][nt], fal[mt], fbh[nt], acc[mt][nt]);
                }
        }
        __syncthreads();
    }

    // Epilogue: stage fp32 tile in smem, then coalesced bias+store
    float* Cs = (float*)smc;           // 128 x 132 fp32 = 67584 B < GEMM_SMEM
    #pragma unroll
    for (int mt = 0; mt < 4; mt++)
        #pragma unroll
        for (int nt = 0; nt < 2; nt++)
            wmma::store_matrix_sync(Cs + (warp_m*64 + mt*16)*132 + warp_n*32 + nt*16,
                                    acc[mt][nt], 132, wmma::mem_row_major);
    __syncthreads();

    const int r  = tid >> 1;            // 0..127
    const int c0 = (tid & 1) * 64;      // 0 or 64
    #pragma unroll
    for (int j = 0; j < 16; j++) {
        const int col = c0 + j * 4;
        float4 v = *(float4*)&Cs[r*132 + col];
        if (bias) {
            const float4 bv = *(const float4*)&bias[bx*128 + col];
            v.x += bv.x; v.y += bv.y; v.z += bv.z; v.w += bv.w;
        }
        *(float4*)&C[(size_t)(by*128 + r) * Nn + bx*128 + col] = v;
    }
}

// ---------------------------------------------------------------------------
// Flash attention, fp32, online softmax (byte-identical to the R1 pass)
// ---------------------------------------------------------------------------
#define FA_PITCH 65
#define FA_SMEM  (3 * 64 * FA_PITCH * 4)   // 49920 bytes

__global__ __launch_bounds__(256)
void flash_fp32(const float* __restrict__ Q,
                const float* __restrict__ K,
                const float* __restrict__ V,
                float* __restrict__ Out)
{
    extern __shared__ float smf[];
    float* Qt  = smf;
    float* KVs = smf + 64 * FA_PITCH;
    float* Ps  = smf + 2 * 64 * FA_PITCH;

    const int tid = threadIdx.x;
    const int tx = tid & 15;
    const int ty = tid >> 4;
    const int q0 = blockIdx.x * 64;
    const int h  = blockIdx.y;
    const int b  = blockIdx.z;

    const float* qbase = Q + ((size_t)(b * SEQ) + q0) * EMB + h * HDIM;
    const float* kbase = K + (size_t)(b * SEQ) * EMB + h * HDIM;
    const float* vbase = V + (size_t)(b * SEQ) * EMB + h * HDIM;

    #pragma unroll
    for (int t = 0; t < 4; t++) {
        int idx = tid + t * 256;
        int r = idx >> 4;
        int c = (idx & 15) * 4;
        float4 qv = *(const float4*)(qbase + (size_t)r * EMB + c);
        Qt[(c + 0) * FA_PITCH + r] = qv.x * 0.125f;
        Qt[(c + 1) * FA_PITCH + r] = qv.y * 0.125f;
        Qt[(c + 2) * FA_PITCH + r] = qv.z * 0.125f;
        Qt[(c + 3) * FA_PITCH + r] = qv.w * 0.125f;
    }

    float m_i[4], l_i[4], acc[4][4];
    #pragma unroll
    for (int i = 0; i < 4; i++) {
        m_i[i] = -INFINITY;
        l_i[i] = 0.f;
        #pragma unroll
        for (int j = 0; j < 4; j++) acc[i][j] = 0.f;
    }
    __syncthreads();

    for (int kv0 = 0; kv0 < SEQ; kv0 += 64) {
        #pragma unroll
        for (int t = 0; t < 4; t++) {
            int idx = tid + t * 256;
            int r = idx >> 4;
            int c = (idx & 15) * 4;
            float4 kv = *(const float4*)(kbase + (size_t)(kv0 + r) * EMB + c);
            KVs[(c + 0) * FA_PITCH + r] = kv.x;
            KVs[(c + 1) * FA_PITCH + r] = kv.y;
            KVs[(c + 2) * FA_PITCH + r] = kv.z;
            KVs[(c + 3) * FA_PITCH + r] = kv.w;
        }
        __syncthreads();

        float s[4][4];
        #pragma unroll
        for (int i = 0; i < 4; i++)
            #pragma unroll
            for (int j = 0; j < 4; j++) s[i][j] = 0.f;

        #pragma unroll 8
        for (int d = 0; d < HDIM; d++) {
            float ra[4], rb[4];
            #pragma unroll
            for (int i = 0; i < 4; i++) ra[i] = Qt[d * FA_PITCH + i * 16 + ty];
            #pragma unroll
            for (int j = 0; j < 4; j++) rb[j] = KVs[d * FA_PITCH + j * 16 + tx];
            #pragma unroll
            for (int i = 0; i < 4; i++)
                #pragma unroll
                for (int j = 0; j < 4; j++)
                    s[i][j] = fmaf(ra[i], rb[j], s[i][j]);
        }

        #pragma unroll
        for (int i = 0; i < 4; i++) {
            float mt = s[i][0];
            #pragma unroll
            for (int j = 1; j < 4; j++) mt = fmaxf(mt, s[i][j]);
            #pragma unroll
            for (int off = 8; off > 0; off >>= 1)
                mt = fmaxf(mt, __shfl_xor_sync(0xffffffffu, mt, off, 16));

            float mn = fmaxf(m_i[i], mt);
            float alpha = __expf(m_i[i] - mn);
            m_i[i] = mn;

            float ls = 0.f;
            #pragma unroll
            for (int j = 0; j < 4; j++) {
                s[i][j] = __expf(s[i][j] - mn);
                ls += s[i][j];
            }
            #pragma unroll
            for (int off = 8; off > 0; off >>= 1)
                ls += __shfl_xor_sync(0xffffffffu, ls, off, 16);
            l_i[i] = l_i[i] * alpha + ls;

            #pragma unroll
            for (int j = 0; j < 4; j++) {
                acc[i][j] *= alpha;
                Ps[(i * 16 + ty) * FA_PITCH + j * 16 + tx] = s[i][j];
            }
        }
        __syncthreads();

        #pragma unroll
        for (int t = 0; t < 4; t++) {
            int idx = tid + t * 256;
            int r = idx >> 4;
            int c = (idx & 15) * 4;
            float4 vv = *(const float4*)(vbase + (size_t)(kv0 + r) * EMB + c);
            KVs[r * FA_PITCH + c + 0] = vv.x;
            KVs[r * FA_PITCH + c + 1] = vv.y;
            KVs[r * FA_PITCH + c + 2] = vv.z;
            KVs[r * FA_PITCH + c + 3] = vv.w;
        }
        __syncthreads();

        #pragma unroll 8
        for (int kv = 0; kv < 64; kv++) {
            float rp[4], rv[4];
            #pragma unroll
            for (int i = 0; i < 4; i++) rp[i] = Ps[(i * 16 + ty) * FA_PITCH + kv];
            #pragma unroll
            for (int j = 0; j < 4; j++) rv[j] = KVs[kv * FA_PITCH + j * 16 + tx];
            #pragma unroll
            for (int i = 0; i < 4; i++)
                #pragma unroll
                for (int j = 0; j < 4; j++)
                    acc[i][j] = fmaf(rp[i], rv[j], acc[i][j]);
        }
        __syncthreads();
    }

    #pragma unroll
    for (int i = 0; i < 4; i++) {
        const float inv = 1.0f / l_i[i];
        const int q = q0 + i * 16 + ty;
        #pragma unroll
        for (int j = 0; j < 4; j++) {
            Out[((size_t)(b * SEQ) + q) * EMB + h * HDIM + j * 16 + tx] =
                acc[i][j] * inv;
        }
    }
}

// ---------------------------------------------------------------------------
extern "C" void kernel_launch(void* const* d_in, const int* in_sizes, int n_in,
                              void* d_out, int out_size)
{
    const float* x  = (const float*)d_in[0];
    const float* Wq = (const float*)d_in[1];
    const float* bq = (const float*)d_in[2];
    const float* Wk = (const float*)d_in[3];
    const float* bk = (const float*)d_in[4];
    const float* Wv = (const float*)d_in[5];
    const float* bv = (const float*)d_in[6];
    const float* Wo = (const float*)d_in[7];
    float* out = (float*)d_out;

    float *qp, *kp, *vp, *aop;
    __nv_bfloat16 *xh, *xl, *wh, *wl;
    cudaGetSymbolAddress((void**)&qp,  g_q);
    cudaGetSymbolAddress((void**)&kp,  g_k);
    cudaGetSymbolAddress((void**)&vp,  g_v);
    cudaGetSymbolAddress((void**)&aop, g_ao);
    cudaGetSymbolAddress((void**)&xh,  g_xh);
    cudaGetSymbolAddress((void**)&xl,  g_xl);
    cudaGetSymbolAddress((void**)&wh,  g_wh);
    cudaGetSymbolAddress((void**)&wl,  g_wl);

    cudaFuncSetAttribute(gemm_wmma,
                         cudaFuncAttributeMaxDynamicSharedMemorySize, GEMM_SMEM);
    cudaFuncSetAttribute(flash_fp32,
                         cudaFuncAttributeMaxDynamicSharedMemorySize, FA_SMEM);

    const int WSZ = EMB * EMB;                       // 1M elems per weight
    const int xn4 = MROWS * EMB / 4;                 // 2M float4
    const int wn4 = WSZ / 4;

    // Split x and weights to bf16 hi/lo
    split_kernel<<<(xn4 + 255) / 256, 256>>>(x, xh, xl, xn4);
    split_kernel<<<(wn4 + 255) / 256, 256>>>(Wq, wh + 0*WSZ, wl + 0*WSZ, wn4);
    split_kernel<<<(wn4 + 255) / 256, 256>>>(Wk, wh + 1*WSZ, wl + 1*WSZ, wn4);
    split_kernel<<<(wn4 + 255) / 256, 256>>>(Wv, wh + 2*WSZ, wl + 2*WSZ, wn4);
    split_kernel<<<(wn4 + 255) / 256, 256>>>(Wo, wh + 3*WSZ, wl + 3*WSZ, wn4);

    dim3 gg(EMB / 128, MROWS / 128);   // (8, 64)
    gemm_wmma<<<gg, 256, GEMM_SMEM>>>(xh, xl, wh + 0*WSZ, wl + 0*WSZ, bq, qp, EMB);
    gemm_wmma<<<gg, 256, GEMM_SMEM>>>(xh, xl, wh + 1*WSZ, wl + 1*WSZ, bk, kp, EMB);
    gemm_wmma<<<gg, 256, GEMM_SMEM>>>(xh, xl, wh + 2*WSZ, wl + 2*WSZ, bv, vp, EMB);

    dim3 fg(SEQ / 64, HEADS, BATCH);   // (32, 16, 4)
    flash_fp32<<<fg, 256, FA_SMEM>>>(qp, kp, vp, aop);

    // x hi/lo are dead now — reuse for the attn-out split
    split_kernel<<<(xn4 + 255) / 256, 256>>>(aop, xh, xl, xn4);
    gemm_wmma<<<gg, 256, GEMM_SMEM>>>(xh, xl, wh + 3*WSZ, wl + 3*WSZ, nullptr, out, EMB);
}

// round 7
// speedup vs baseline: 1.6379x; 1.2006x over previous
#include <cuda_runtime.h>
#include <cuda_bf16.h>
#include <cuda_pipeline.h>
#include <mma.h>
#include <math.h>
#include <stdint.h>

using namespace nvcuda;

// Problem constants
#define BATCH 4
#define SEQ   2048
#define EMB   1024
#define HEADS 16
#define HDIM  64
#define MROWS (BATCH*SEQ)   // 8192

// ---------------------------------------------------------------------------
// Scratch (device globals). All q/k/v scratch is bf16 hi/lo now; no fp32
// intermediates. attn-out hi/lo reuse x hi/lo (dead after 3rd QKV GEMM).
// ---------------------------------------------------------------------------
__device__ __nv_bfloat16 g_qh[MROWS*EMB], g_ql[MROWS*EMB];
__device__ __nv_bfloat16 g_kh[MROWS*EMB], g_kl[MROWS*EMB];
__device__ __nv_bfloat16 g_vh[MROWS*EMB], g_vl[MROWS*EMB];
__device__ __nv_bfloat16 g_xh[MROWS*EMB], g_xl[MROWS*EMB];
__device__ __nv_bfloat16 g_wh[4*EMB*EMB], g_wl[4*EMB*EMB];

// ---------------------------------------------------------------------------
// Split fp32 -> (bf16 hi, bf16 lo)
// ---------------------------------------------------------------------------
__global__ __launch_bounds__(256)
void split_kernel(const float* __restrict__ src,
                  __nv_bfloat16* __restrict__ hi,
                  __nv_bfloat16* __restrict__ lo, int n4)
{
    int i = blockIdx.x * blockDim.x + threadIdx.x;
    if (i >= n4) return;
    float4 v = ((const float4*)src)[i];
    __nv_bfloat16 h0 = __float2bfloat16(v.x);
    __nv_bfloat16 h1 = __float2bfloat16(v.y);
    __nv_bfloat16 h2 = __float2bfloat16(v.z);
    __nv_bfloat16 h3 = __float2bfloat16(v.w);
    __nv_bfloat16 l0 = __float2bfloat16(v.x - __bfloat162float(h0));
    __nv_bfloat16 l1 = __float2bfloat16(v.y - __bfloat162float(h1));
    __nv_bfloat16 l2 = __float2bfloat16(v.z - __bfloat162float(h2));
    __nv_bfloat16 l3 = __float2bfloat16(v.w - __bfloat162float(h3));
    __nv_bfloat162* hp = (__nv_bfloat162*)hi;
    __nv_bfloat162* lp = (__nv_bfloat162*)lo;
    __nv_bfloat162 a; a.x = h0; a.y = h1;
    __nv_bfloat162 b; b.x = h2; b.y = h3;
    __nv_bfloat162 c; c.x = l0; c.y = l1;
    __nv_bfloat162 d; d.x = l2; d.y = l3;
    hp[i*2+0] = a; hp[i*2+1] = b;
    lp[i*2+0] = c; lp[i*2+1] = d;
}

// ---------------------------------------------------------------------------
// WMMA split-bf16 GEMM (proven R6 core). New: optional bf16 hi/lo output
// epilogue with scale (for q/k/v), else fp32 output.
// ---------------------------------------------------------------------------
#define NCHUNKS   (EMB/32)            // 32
#define PITCH_E   48
#define TILE_SB   (128*PITCH_E*2)     // 12288
#define STAGE_SB  (4*TILE_SB)         // 49152
#define GEMM_SMEM (2*STAGE_SB)        // 98304

__global__ __launch_bounds__(256)
void gemm_wmma(const __nv_bfloat16* __restrict__ Ah, const __nv_bfloat16* __restrict__ Al,
               const __nv_bfloat16* __restrict__ Bh, const __nv_bfloat16* __restrict__ Bl,
               const float* __restrict__ bias,
               float* __restrict__ Cf,
               __nv_bfloat16* __restrict__ outH, __nv_bfloat16* __restrict__ outL,
               float scale, int Nn)
{
    extern __shared__ char smc[];
    const int tid  = threadIdx.x;
    const int wid  = tid >> 5;
    const int warp_m = wid >> 2;
    const int warp_n = wid & 3;
    const int bx = blockIdx.x;
    const int by = blockIdx.y;

    const char* ahg = (const char*)Ah + (size_t)(by*128) * 2048;
    const char* alg = (const char*)Al + (size_t)(by*128) * 2048;
    const char* bhg = (const char*)Bh + (size_t)(bx*128) * 2048;
    const char* blg = (const char*)Bl + (size_t)(bx*128) * 2048;

    int lrow[2], lcb[2];
    #pragma unroll
    for (int i = 0; i < 2; i++) {
        int idx = tid + i * 256;
        lrow[i] = idx >> 2;
        lcb[i]  = (idx & 3) * 16;
    }

    auto load_chunk = [&](int c, int stage) {
        char* st = smc + stage * STAGE_SB;
        const int ko = c * 64;
        #pragma unroll
        for (int i = 0; i < 2; i++) {
            const int    so = lrow[i] * (PITCH_E*2) + lcb[i];
            const size_t go = (size_t)lrow[i] * 2048 + ko + lcb[i];
            __pipeline_memcpy_async(st + 0*TILE_SB + so, ahg + go, 16);
            __pipeline_memcpy_async(st + 1*TILE_SB + so, alg + go, 16);
            __pipeline_memcpy_async(st + 2*TILE_SB + so, bhg + go, 16);
            __pipeline_memcpy_async(st + 3*TILE_SB + so, blg + go, 16);
        }
        __pipeline_commit();
    };

    wmma::fragment<wmma::accumulator, 16, 16, 16, float> acc[4][2];
    #pragma unroll
    for (int mt = 0; mt < 4; mt++)
        #pragma unroll
        for (int nt = 0; nt < 2; nt++)
            wmma::fill_fragment(acc[mt][nt], 0.0f);

    load_chunk(0, 0);

    for (int c = 0; c < NCHUNKS; c++) {
        if (c + 1 < NCHUNKS) {
            load_chunk(c + 1, (c + 1) & 1);
            __pipeline_wait_prior(1);
        } else {
            __pipeline_wait_prior(0);
        }
        __syncthreads();

        char* st = smc + (c & 1) * STAGE_SB;
        const __nv_bfloat16* ahs = (const __nv_bfloat16*)(st + 0*TILE_SB);
        const __nv_bfloat16* als = (const __nv_bfloat16*)(st + 1*TILE_SB);
        const __nv_bfloat16* bhs = (const __nv_bfloat16*)(st + 2*TILE_SB);
        const __nv_bfloat16* bls = (const __nv_bfloat16*)(st + 3*TILE_SB);

        #pragma unroll
        for (int ks = 0; ks < 2; ks++) {
            const int ke = ks * 16;

            wmma::fragment<wmma::matrix_a, 16, 16, 16, __nv_bfloat16, wmma::row_major> fah[4], fal[4];
            #pragma unroll
            for (int mt = 0; mt < 4; mt++) {
                const int ro = (warp_m*64 + mt*16) * PITCH_E + ke;
                wmma::load_matrix_sync(fah[mt], ahs + ro, PITCH_E);
                wmma::load_matrix_sync(fal[mt], als + ro, PITCH_E);
            }
            wmma::fragment<wmma::matrix_b, 16, 16, 16, __nv_bfloat16, wmma::col_major> fbh[2], fbl[2];
            #pragma unroll
            for (int nt = 0; nt < 2; nt++) {
                const int ro = (warp_n*32 + nt*16) * PITCH_E + ke;
                wmma::load_matrix_sync(fbh[nt], bhs + ro, PITCH_E);
                wmma::load_matrix_sync(fbl[nt], bls + ro, PITCH_E);
            }

            #pragma unroll
            for (int mt = 0; mt < 4; mt++)
                #pragma unroll
                for (int nt = 0; nt < 2; nt++) {
                    wmma::mma_sync(acc[mt][nt], fah[mt], fbh[nt], acc[mt][nt]);
                    wmma::mma_sync(acc[mt][nt], fah[mt], fbl[nt], acc[mt][nt]);
                    wmma::mma_sync(acc[mt][nt], fal[mt], fbh[nt], acc[mt][nt]);
                }
        }
        __syncthreads();
    }

    // Stage tile to smem fp32
    float* Cs = (float*)smc;   // 128 x 132
    #pragma unroll
    for (int mt = 0; mt < 4; mt++)
        #pragma unroll
        for (int nt = 0; nt < 2; nt++)
            wmma::store_matrix_sync(Cs + (warp_m*64 + mt*16)*132 + warp_n*32 + nt*16,
                                    acc[mt][nt], 132, wmma::mem_row_major);
    __syncthreads();

    const int r  = tid >> 1;
    const int c0 = (tid & 1) * 64;
    if (outH == nullptr) {
        #pragma unroll
        for (int j = 0; j < 16; j++) {
            const int col = c0 + j * 4;
            float4 v = *(float4*)&Cs[r*132 + col];
            if (bias) {
                const float4 bv = *(const float4*)&bias[bx*128 + col];
                v.x += bv.x; v.y += bv.y; v.z += bv.z; v.w += bv.w;
            }
            *(float4*)&Cf[(size_t)(by*128 + r) * Nn + bx*128 + col] = v;
        }
    } else {
        #pragma unroll
        for (int j = 0; j < 16; j++) {
            const int col = c0 + j * 4;
            float4 v = *(float4*)&Cs[r*132 + col];
            if (bias) {
                const float4 bv = *(const float4*)&bias[bx*128 + col];
                v.x += bv.x; v.y += bv.y; v.z += bv.z; v.w += bv.w;
            }
            v.x *= scale; v.y *= scale; v.z *= scale; v.w *= scale;
            __nv_bfloat16 h0 = __float2bfloat16(v.x), h1 = __float2bfloat16(v.y);
            __nv_bfloat16 h2 = __float2bfloat16(v.z), h3 = __float2bfloat16(v.w);
            __nv_bfloat162 hp0; hp0.x = h0; hp0.y = h1;
            __nv_bfloat162 hp1; hp1.x = h2; hp1.y = h3;
            __nv_bfloat162 lp0, lp1;
            lp0.x = __float2bfloat16(v.x - __bfloat162float(h0));
            lp0.y = __float2bfloat16(v.y - __bfloat162float(h1));
            lp1.x = __float2bfloat16(v.z - __bfloat162float(h2));
            lp1.y = __float2bfloat16(v.w - __bfloat162float(h3));
            const size_t o = (size_t)(by*128 + r) * Nn + bx*128 + col;
            *(__nv_bfloat162*)&outH[o]     = hp0;
            *(__nv_bfloat162*)&outH[o + 2] = hp1;
            *(__nv_bfloat162*)&outL[o]     = lp0;
            *(__nv_bfloat162*)&outL[o + 2] = lp1;
        }
    }
}

// ---------------------------------------------------------------------------
// WMMA flash attention. Block = 64 q-rows x one (b,h). KV tiles of 64.
// 8 warps (2m x 4n). S and PV both 3-pass split-bf16 wmma. O kept in smem
// fp32 (rescaled by alpha there); softmax by 4 threads/row.
// Q arrives pre-scaled by 0.125. Writes attn-out as bf16 hi/lo.
// ---------------------------------------------------------------------------
#define FW_PITCH  72     // bf16 elems per smem row (144 B)
#define FW_FPITCH 68     // fp32 elems per smem row (272 B)
// smem byte offsets
#define SQH 0
#define SQL 9216
#define SKH 18432
#define SKL 27648
#define SVH 36864
#define SVL 46080
#define SSS 55296        // 64x68 fp32 = 17408
#define SPH 72704        // 64x72 bf16 = 9216
#define SPL 81920
#define SOS 91136        // 64x68 fp32 = 17408
#define SMM 108544       // 64 fp32
#define SLL 108800       // 64 fp32
#define FW_SMEM 109056

__global__ __launch_bounds__(256)
void flash_wmma(const __nv_bfloat16* __restrict__ Qh, const __nv_bfloat16* __restrict__ Ql,
                const __nv_bfloat16* __restrict__ Kh, const __nv_bfloat16* __restrict__ Kl,
                const __nv_bfloat16* __restrict__ Vh, const __nv_bfloat16* __restrict__ Vl,
                __nv_bfloat16* __restrict__ Oh, __nv_bfloat16* __restrict__ Ol)
{
    extern __shared__ char smw[];
    const int tid  = threadIdx.x;
    const int wid  = tid >> 5;
    const int warp_m = wid >> 2;       // 0..1
    const int warp_n = wid & 3;        // 0..3
    const int q0 = blockIdx.x * 64;
    const int h  = blockIdx.y;
    const int b  = blockIdx.z;

    __nv_bfloat16* sQh = (__nv_bfloat16*)(smw + SQH);
    __nv_bfloat16* sQl = (__nv_bfloat16*)(smw + SQL);
    __nv_bfloat16* sKh = (__nv_bfloat16*)(smw + SKH);
    __nv_bfloat16* sKl = (__nv_bfloat16*)(smw + SKL);
    __nv_bfloat16* sVh = (__nv_bfloat16*)(smw + SVH);
    __nv_bfloat16* sVl = (__nv_bfloat16*)(smw + SVL);
    float* sS  = (float*)(smw + SSS);
    __nv_bfloat16* sPh = (__nv_bfloat16*)(smw + SPH);
    __nv_bfloat16* sPl = (__nv_bfloat16*)(smw + SPL);
    float* sO  = (float*)(smw + SOS);
    float* sM  = (float*)(smw + SMM);
    float* sL  = (float*)(smw + SLL);

    // loader slots: 64 rows x 128 B per array -> 512 x16B chunks, 2/thread
    const int lr0 = tid >> 3,           lc0 = (tid & 7) * 16;
    const int lr1 = (tid + 256) >> 3,   lc1 = ((tid + 256) & 7) * 16;

    const size_t hoff = (size_t)h * HDIM;
    const size_t brow = (size_t)(b * SEQ);

    auto issueK = [&](int t) {
        const size_t g0 = (brow + t*64 + lr0) * EMB + hoff;
        const size_t g1 = (brow + t*64 + lr1) * EMB + hoff;
        __pipeline_memcpy_async(smw + SKH + lr0*144 + lc0, (const char*)Kh + g0*2 + lc0, 16);
        __pipeline_memcpy_async(smw + SKL + lr0*144 + lc0, (const char*)Kl + g0*2 + lc0, 16);
        __pipeline_memcpy_async(smw + SKH + lr1*144 + lc1, (const char*)Kh + g1*2 + lc1, 16);
        __pipeline_memcpy_async(smw + SKL + lr1*144 + lc1, (const char*)Kl + g1*2 + lc1, 16);
        __pipeline_commit();
    };
    auto issueV = [&](int t) {
        const size_t g0 = (brow + t*64 + lr0) * EMB + hoff;
        const size_t g1 = (brow + t*64 + lr1) * EMB + hoff;
        __pipeline_memcpy_async(smw + SVH + lr0*144 + lc0, (const char*)Vh + g0*2 + lc0, 16);
        __pipeline_memcpy_async(smw + SVL + lr0*144 + lc0, (const char*)Vl + g0*2 + lc0, 16);
        __pipeline_memcpy_async(smw + SVH + lr1*144 + lc1, (const char*)Vh + g1*2 + lc1, 16);
        __pipeline_memcpy_async(smw + SVL + lr1*144 + lc1, (const char*)Vl + g1*2 + lc1, 16);
        __pipeline_commit();
    };

    issueK(0);

    // load Q (plain) + init O/m/l
    {
        const size_t g0 = (brow + q0 + lr0) * EMB + hoff;
        const size_t g1 = (brow + q0 + lr1) * EMB + hoff;
        *(uint4*)(smw + SQH + lr0*144 + lc0) = *(const uint4*)((const char*)Qh + g0*2 + lc0);
        *(uint4*)(smw + SQL + lr0*144 + lc0) = *(const uint4*)((const char*)Ql + g0*2 + lc0);
        *(uint4*)(smw + SQH + lr1*144 + lc1) = *(const uint4*)((const char*)Qh + g1*2 + lc1);
        *(uint4*)(smw + SQL + lr1*144 + lc1) = *(const uint4*)((const char*)Ql + g1*2 + lc1);
    }
    for (int i = tid; i < 64*FW_FPITCH; i += 256) sO[i] = 0.f;
    if (tid < 64) { sM[tid] = -INFINITY; sL[tid] = 0.f; }
    __syncthreads();

    const int srow = tid >> 2;          // softmax row
    const int ssub = tid & 3;
    const int sc0  = ssub * 16;

    for (int t = 0; t < SEQ/64; t++) {
        __pipeline_wait_prior(0);       // K_t resident
        __syncthreads();
        issueV(t);

        // ---- S = Q K^T (3-pass split), per warp 2 tiles of 16x16
        #pragma unroll
        for (int mt = 0; mt < 2; mt++) {
            wmma::fragment<wmma::accumulator, 16, 16, 16, float> sc;
            wmma::fill_fragment(sc, 0.f);
            #pragma unroll
            for (int ks = 0; ks < 4; ks++) {
                wmma::fragment<wmma::matrix_a, 16, 16, 16, __nv_bfloat16, wmma::row_major> ah, al;
                const int ro = (warp_m*32 + mt*16) * FW_PITCH + ks*16;
                wmma::load_matrix_sync(ah, sQh + ro, FW_PITCH);
                wmma::load_matrix_sync(al, sQl + ro, FW_PITCH);
                wmma::fragment<wmma::matrix_b, 16, 16, 16, __nv_bfloat16, wmma::col_major> bh, bl;
                const int co = (warp_n*16) * FW_PITCH + ks*16;
                wmma::load_matrix_sync(bh, sKh + co, FW_PITCH);
                wmma::load_matrix_sync(bl, sKl + co, FW_PITCH);
                wmma::mma_sync(sc, ah, bh, sc);
                wmma::mma_sync(sc, ah, bl, sc);
                wmma::mma_sync(sc, al, bh, sc);
            }
            wmma::store_matrix_sync(sS + (warp_m*32 + mt*16)*FW_FPITCH + warp_n*16,
                                    sc, FW_FPITCH, wmma::mem_row_major);
        }
        __syncthreads();

        // ---- online softmax (4 threads per row)
        {
            float mt_ = -INFINITY;
            #pragma unroll
            for (int j = 0; j < 16; j++)
                mt_ = fmaxf(mt_, sS[srow*FW_FPITCH + sc0 + j]);
            mt_ = fmaxf(mt_, __shfl_xor_sync(0xffffffffu, mt_, 1, 4));
            mt_ = fmaxf(mt_, __shfl_xor_sync(0xffffffffu, mt_, 2, 4));

            const float m_old = sM[srow];
            const float m_new = fmaxf(m_old, mt_);
            const float alpha = __expf(m_old - m_new);

            float ls = 0.f;
            #pragma unroll
            for (int j = 0; j < 16; j++) {
                const float p = __expf(sS[srow*FW_FPITCH + sc0 + j] - m_new);
                ls += p;
                const __nv_bfloat16 ph = __float2bfloat16(p);
                sPh[srow*FW_PITCH + sc0 + j] = ph;
                sPl[srow*FW_PITCH + sc0 + j] = __float2bfloat16(p - __bfloat162float(ph));
            }
            ls += __shfl_xor_sync(0xffffffffu, ls, 1, 4);
            ls += __shfl_xor_sync(0xffffffffu, ls, 2, 4);
            if (ssub == 0) { sM[srow] = m_new; sL[srow] = sL[srow] * alpha + ls; }

            #pragma unroll
            for (int j = 0; j < 16; j++)
                sO[srow*FW_FPITCH + sc0 + j] *= alpha;
        }

        __pipeline_wait_prior(0);       // V_t resident
        __syncthreads();                // P, O-scale, V all visible
        if (t + 1 < SEQ/64) issueK(t + 1);

        // ---- O += P V (3-pass split)
        #pragma unroll
        for (int mt = 0; mt < 2; mt++) {
            wmma::fragment<wmma::accumulator, 16, 16, 16, float> oc;
            wmma::load_matrix_sync(oc, sO + (warp_m*32 + mt*16)*FW_FPITCH + warp_n*16,
                                   FW_FPITCH, wmma::mem_row_major);
            #pragma unroll
            for (int ks = 0; ks < 4; ks++) {
                wmma::fragment<wmma::matrix_a, 16, 16, 16, __nv_bfloat16, wmma::row_major> ph, pl;
                const int ro = (warp_m*32 + mt*16) * FW_PITCH + ks*16;
                wmma::load_matrix_sync(ph, sPh + ro, FW_PITCH);
                wmma::load_matrix_sync(pl, sPl + ro, FW_PITCH);
                wmma::fragment<wmma::matrix_b, 16, 16, 16, __nv_bfloat16, wmma::row_major> vh, vl;
                const int vo = (ks*16) * FW_PITCH + warp_n*16;
                wmma::load_matrix_sync(vh, sVh + vo, FW_PITCH);
                wmma::load_matrix_sync(vl, sVl + vo, FW_PITCH);
                wmma::mma_sync(oc, ph, vh, oc);
                wmma::mma_sync(oc, ph, vl, oc);
                wmma::mma_sync(oc, pl, vh, oc);
            }
            wmma::store_matrix_sync(sO + (warp_m*32 + mt*16)*FW_FPITCH + warp_n*16,
                                    oc, FW_FPITCH, wmma::mem_row_major);
        }
        __syncthreads();
    }

    // ---- epilogue: normalize, split to bf16 hi/lo, store
    {
        const float inv = 1.0f / sL[srow];
        const size_t o = (brow + q0 + srow) * EMB + hoff + sc0;
        #pragma unroll
        for (int j = 0; j < 16; j += 2) {
            float v0 = sO[srow*FW_FPITCH + sc0 + j]     * inv;
            float v1 = sO[srow*FW_FPITCH + sc0 + j + 1] * inv;
            __nv_bfloat162 hp, lp;
            hp.x = __float2bfloat16(v0);
            hp.y = __float2bfloat16(v1);
            lp.x = __float2bfloat16(v0 - __bfloat162float(hp.x));
            lp.y = __float2bfloat16(v1 - __bfloat162float(hp.y));
            *(__nv_bfloat162*)&Oh[o + j] = hp;
            *(__nv_bfloat162*)&Ol[o + j] = lp;
        }
    }
}

// ---------------------------------------------------------------------------
extern "C" void kernel_launch(void* const* d_in, const int* in_sizes, int n_in,
                              void* d_out, int out_size)
{
    const float* x  = (const float*)d_in[0];
    const float* Wq = (const float*)d_in[1];
    const float* bq = (const float*)d_in[2];
    const float* Wk = (const float*)d_in[3];
    const float* bk = (const float*)d_in[4];
    const float* Wv = (const float*)d_in[5];
    const float* bv = (const float*)d_in[6];
    const float* Wo = (const float*)d_in[7];
    float* out = (float*)d_out;

    __nv_bfloat16 *qh, *ql, *kh, *kl, *vh, *vl, *xh, *xl, *wh, *wl;
    cudaGetSymbolAddress((void**)&qh, g_qh);
    cudaGetSymbolAddress((void**)&ql, g_ql);
    cudaGetSymbolAddress((void**)&kh, g_kh);
    cudaGetSymbolAddress((void**)&kl, g_kl);
    cudaGetSymbolAddress((void**)&vh, g_vh);
    cudaGetSymbolAddress((void**)&vl, g_vl);
    cudaGetSymbolAddress((void**)&xh, g_xh);
    cudaGetSymbolAddress((void**)&xl, g_xl);
    cudaGetSymbolAddress((void**)&wh, g_wh);
    cudaGetSymbolAddress((void**)&wl, g_wl);

    cudaFuncSetAttribute(gemm_wmma,
                         cudaFuncAttributeMaxDynamicSharedMemorySize, GEMM_SMEM);
    cudaFuncSetAttribute(flash_wmma,
                         cudaFuncAttributeMaxDynamicSharedMemorySize, FW_SMEM);

    const int WSZ = EMB * EMB;
    const int xn4 = MROWS * EMB / 4;
    const int wn4 = WSZ / 4;

    split_kernel<<<(xn4 + 255) / 256, 256>>>(x, xh, xl, xn4);
    split_kernel<<<(wn4 + 255) / 256, 256>>>(Wq, wh + 0*WSZ, wl + 0*WSZ, wn4);
    split_kernel<<<(wn4 + 255) / 256, 256>>>(Wk, wh + 1*WSZ, wl + 1*WSZ, wn4);
    split_kernel<<<(wn4 + 255) / 256, 256>>>(Wv, wh + 2*WSZ, wl + 2*WSZ, wn4);
    split_kernel<<<(wn4 + 255) / 256, 256>>>(Wo, wh + 3*WSZ, wl + 3*WSZ, wn4);

    dim3 gg(EMB / 128, MROWS / 128);   // (8, 64)
    // Q pre-scaled by 1/sqrt(Dh) = 0.125 (exact power of two)
    gemm_wmma<<<gg, 256, GEMM_SMEM>>>(xh, xl, wh + 0*WSZ, wl + 0*WSZ, bq,
                                      nullptr, qh, ql, 0.125f, EMB);
    gemm_wmma<<<gg, 256, GEMM_SMEM>>>(xh, xl, wh + 1*WSZ, wl + 1*WSZ, bk,
                                      nullptr, kh, kl, 1.0f, EMB);
    gemm_wmma<<<gg, 256, GEMM_SMEM>>>(xh, xl, wh + 2*WSZ, wl + 2*WSZ, bv,
                                      nullptr, vh, vl, 1.0f, EMB);

    dim3 fg(SEQ / 64, HEADS, BATCH);   // (32, 16, 4)
    // attn-out hi/lo land in xh/xl (x's bf16 copies are dead now)
    flash_wmma<<<fg, 256, FW_SMEM>>>(qh, ql, kh, kl, vh, vl, xh, xl);

    gemm_wmma<<<gg, 256, GEMM_SMEM>>>(xh, xl, wh + 3*WSZ, wl + 3*WSZ, nullptr,
                                      out, nullptr, nullptr, 1.0f, EMB);
}

// round 9
// speedup vs baseline: 1.8192x; 1.1107x over previous
#include <cuda_runtime.h>
#include <cuda_bf16.h>
#include <cuda_pipeline.h>
#include <mma.h>
#include <math.h>
#include <stdint.h>

using namespace nvcuda;

// Problem constants
#define BATCH 4
#define SEQ   2048
#define EMB   1024
#define HEADS 16
#define HDIM  64
#define MROWS (BATCH*SEQ)   // 8192

// ---------------------------------------------------------------------------
// Scratch (device globals)
// ---------------------------------------------------------------------------
__device__ __nv_bfloat16 g_qh[MROWS*EMB], g_ql[MROWS*EMB];
__device__ __nv_bfloat16 g_kh[MROWS*EMB], g_kl[MROWS*EMB];
__device__ __nv_bfloat16 g_vh[MROWS*EMB], g_vl[MROWS*EMB];
__device__ __nv_bfloat16 g_xh[MROWS*EMB], g_xl[MROWS*EMB];
__device__ __nv_bfloat16 g_wh[4*EMB*EMB], g_wl[4*EMB*EMB];

// ---------------------------------------------------------------------------
// Split fp32 -> (bf16 hi, bf16 lo)
// ---------------------------------------------------------------------------
__global__ __launch_bounds__(256)
void split_kernel(const float* __restrict__ src,
                  __nv_bfloat16* __restrict__ hi,
                  __nv_bfloat16* __restrict__ lo, int n4)
{
    int i = blockIdx.x * blockDim.x + threadIdx.x;
    if (i >= n4) return;
    float4 v = ((const float4*)src)[i];
    __nv_bfloat16 h0 = __float2bfloat16(v.x);
    __nv_bfloat16 h1 = __float2bfloat16(v.y);
    __nv_bfloat16 h2 = __float2bfloat16(v.z);
    __nv_bfloat16 h3 = __float2bfloat16(v.w);
    __nv_bfloat16 l0 = __float2bfloat16(v.x - __bfloat162float(h0));
    __nv_bfloat16 l1 = __float2bfloat16(v.y - __bfloat162float(h1));
    __nv_bfloat16 l2 = __float2bfloat16(v.z - __bfloat162float(h2));
    __nv_bfloat16 l3 = __float2bfloat16(v.w - __bfloat162float(h3));
    __nv_bfloat162* hp = (__nv_bfloat162*)hi;
    __nv_bfloat162* lp = (__nv_bfloat162*)lo;
    __nv_bfloat162 a; a.x = h0; a.y = h1;
    __nv_bfloat162 b; b.x = h2; b.y = h3;
    __nv_bfloat162 c; c.x = l0; c.y = l1;
    __nv_bfloat162 d; d.x = l2; d.y = l3;
    hp[i*2+0] = a; hp[i*2+1] = b;
    lp[i*2+0] = c; lp[i*2+1] = d;
}

// ---------------------------------------------------------------------------
// WMMA split-bf16 GEMM (proven). Optional bf16 hi/lo epilogue with scale.
// ---------------------------------------------------------------------------
#define NCHUNKS   (EMB/32)
#define PITCH_E   48
#define TILE_SB   (128*PITCH_E*2)
#define STAGE_SB  (4*TILE_SB)
#define GEMM_SMEM (2*STAGE_SB)

__global__ __launch_bounds__(256)
void gemm_wmma(const __nv_bfloat16* __restrict__ Ah, const __nv_bfloat16* __restrict__ Al,
               const __nv_bfloat16* __restrict__ Bh, const __nv_bfloat16* __restrict__ Bl,
               const float* __restrict__ bias,
               float* __restrict__ Cf,
               __nv_bfloat16* __restrict__ outH, __nv_bfloat16* __restrict__ outL,
               float scale, int Nn)
{
    extern __shared__ char smc[];
    const int tid  = threadIdx.x;
    const int wid  = tid >> 5;
    const int warp_m = wid >> 2;
    const int warp_n = wid & 3;
    const int bx = blockIdx.x;
    const int by = blockIdx.y;

    const char* ahg = (const char*)Ah + (size_t)(by*128) * 2048;
    const char* alg = (const char*)Al + (size_t)(by*128) * 2048;
    const char* bhg = (const char*)Bh + (size_t)(bx*128) * 2048;
    const char* blg = (const char*)Bl + (size_t)(bx*128) * 2048;

    int lrow[2], lcb[2];
    #pragma unroll
    for (int i = 0; i < 2; i++) {
        int idx = tid + i * 256;
        lrow[i] = idx >> 2;
        lcb[i]  = (idx & 3) * 16;
    }

    auto load_chunk = [&](int c, int stage) {
        char* st = smc + stage * STAGE_SB;
        const int ko = c * 64;
        #pragma unroll
        for (int i = 0; i < 2; i++) {
            const int    so = lrow[i] * (PITCH_E*2) + lcb[i];
            const size_t go = (size_t)lrow[i] * 2048 + ko + lcb[i];
            __pipeline_memcpy_async(st + 0*TILE_SB + so, ahg + go, 16);
            __pipeline_memcpy_async(st + 1*TILE_SB + so, alg + go, 16);
            __pipeline_memcpy_async(st + 2*TILE_SB + so, bhg + go, 16);
            __pipeline_memcpy_async(st + 3*TILE_SB + so, blg + go, 16);
        }
        __pipeline_commit();
    };

    wmma::fragment<wmma::accumulator, 16, 16, 16, float> acc[4][2];
    #pragma unroll
    for (int mt = 0; mt < 4; mt++)
        #pragma unroll
        for (int nt = 0; nt < 2; nt++)
            wmma::fill_fragment(acc[mt][nt], 0.0f);

    load_chunk(0, 0);

    for (int c = 0; c < NCHUNKS; c++) {
        if (c + 1 < NCHUNKS) {
            load_chunk(c + 1, (c + 1) & 1);
            __pipeline_wait_prior(1);
        } else {
            __pipeline_wait_prior(0);
        }
        __syncthreads();

        char* st = smc + (c & 1) * STAGE_SB;
        const __nv_bfloat16* ahs = (const __nv_bfloat16*)(st + 0*TILE_SB);
        const __nv_bfloat16* als = (const __nv_bfloat16*)(st + 1*TILE_SB);
        const __nv_bfloat16* bhs = (const __nv_bfloat16*)(st + 2*TILE_SB);
        const __nv_bfloat16* bls = (const __nv_bfloat16*)(st + 3*TILE_SB);

        #pragma unroll
        for (int ks = 0; ks < 2; ks++) {
            const int ke = ks * 16;

            wmma::fragment<wmma::matrix_a, 16, 16, 16, __nv_bfloat16, wmma::row_major> fah[4], fal[4];
            #pragma unroll
            for (int mt = 0; mt < 4; mt++) {
                const int ro = (warp_m*64 + mt*16) * PITCH_E + ke;
                wmma::load_matrix_sync(fah[mt], ahs + ro, PITCH_E);
                wmma::load_matrix_sync(fal[mt], als + ro, PITCH_E);
            }
            wmma::fragment<wmma::matrix_b, 16, 16, 16, __nv_bfloat16, wmma::col_major> fbh[2], fbl[2];
            #pragma unroll
            for (int nt = 0; nt < 2; nt++) {
                const int ro = (warp_n*32 + nt*16) * PITCH_E + ke;
                wmma::load_matrix_sync(fbh[nt], bhs + ro, PITCH_E);
                wmma::load_matrix_sync(fbl[nt], bls + ro, PITCH_E);
            }

            #pragma unroll
            for (int mt = 0; mt < 4; mt++)
                #pragma unroll
                for (int nt = 0; nt < 2; nt++) {
                    wmma::mma_sync(acc[mt][nt], fah[mt], fbh[nt], acc[mt][nt]);
                    wmma::mma_sync(acc[mt][nt], fah[mt], fbl[nt], acc[mt][nt]);
                    wmma::mma_sync(acc[mt][nt], fal[mt], fbh[nt], acc[mt][nt]);
                }
        }
        __syncthreads();
    }

    float* Cs = (float*)smc;
    #pragma unroll
    for (int mt = 0; mt < 4; mt++)
        #pragma unroll
        for (int nt = 0; nt < 2; nt++)
            wmma::store_matrix_sync(Cs + (warp_m*64 + mt*16)*132 + warp_n*32 + nt*16,
                                    acc[mt][nt], 132, wmma::mem_row_major);
    __syncthreads();

    const int r  = tid >> 1;
    const int c0 = (tid & 1) * 64;
    if (outH == nullptr) {
        #pragma unroll
        for (int j = 0; j < 16; j++) {
            const int col = c0 + j * 4;
            float4 v = *(float4*)&Cs[r*132 + col];
            if (bias) {
                const float4 bv = *(const float4*)&bias[bx*128 + col];
                v.x += bv.x; v.y += bv.y; v.z += bv.z; v.w += bv.w;
            }
            *(float4*)&Cf[(size_t)(by*128 + r) * Nn + bx*128 + col] = v;
        }
    } else {
        #pragma unroll
        for (int j = 0; j < 16; j++) {
            const int col = c0 + j * 4;
            float4 v = *(float4*)&Cs[r*132 + col];
            if (bias) {
                const float4 bv = *(const float4*)&bias[bx*128 + col];
                v.x += bv.x; v.y += bv.y; v.z += bv.z; v.w += bv.w;
            }
            v.x *= scale; v.y *= scale; v.z *= scale; v.w *= scale;
            __nv_bfloat16 h0 = __float2bfloat16(v.x), h1 = __float2bfloat16(v.y);
            __nv_bfloat16 h2 = __float2bfloat16(v.z), h3 = __float2bfloat16(v.w);
            __nv_bfloat162 hp0; hp0.x = h0; hp0.y = h1;
            __nv_bfloat162 hp1; hp1.x = h2; hp1.y = h3;
            __nv_bfloat162 lp0, lp1;
            lp0.x = __float2bfloat16(v.x - __bfloat162float(h0));
            lp0.y = __float2bfloat16(v.y - __bfloat162float(h1));
            lp1.x = __float2bfloat16(v.z - __bfloat162float(h2));
            lp1.y = __float2bfloat16(v.w - __bfloat162float(h3));
            const size_t o = (size_t)(by*128 + r) * Nn + bx*128 + col;
            *(__nv_bfloat162*)&outH[o]     = hp0;
            *(__nv_bfloat162*)&outH[o + 2] = hp1;
            *(__nv_bfloat162*)&outL[o]     = lp0;
            *(__nv_bfloat162*)&outL[o + 2] = lp1;
        }
    }
}

// ---------------------------------------------------------------------------
// WMMA flash v2: 128 q-rows per CTA, 512 threads (4x4 warps), KV tiles of 64.
// O lives in REGISTERS across the whole KV loop (per-element row indices
// discovered once via a probe accumulator load); alpha rescale in registers.
// ---------------------------------------------------------------------------
#define FW_PITCH  72
#define FW_FPITCH 68
// smem byte offsets
#define SQH 0                 // 128x144
#define SQL 18432
#define SKH 36864             // 64x144
#define SKL 46080
#define SVH 55296
#define SVL 64512
#define SSS 73728             // 128x68 fp32 = 34816 (S scores; O staging; probe)
#define SPH 108544            // 128x144 bf16
#define SPL 126976
#define SMM 145408            // 128 fp32
#define SLL 145920
#define SAL 146432
#define FW_SMEM 146944

__global__ __launch_bounds__(512)
void flash_wmma(const __nv_bfloat16* __restrict__ Qh, const __nv_bfloat16* __restrict__ Ql,
                const __nv_bfloat16* __restrict__ Kh, const __nv_bfloat16* __restrict__ Kl,
                const __nv_bfloat16* __restrict__ Vh, const __nv_bfloat16* __restrict__ Vl,
                __nv_bfloat16* __restrict__ Oh, __nv_bfloat16* __restrict__ Ol)
{
    extern __shared__ char smw[];
    const int tid  = threadIdx.x;
    const int wid  = tid >> 5;
    const int warp_m = wid >> 2;       // 0..3  (32 q-rows each)
    const int warp_n = wid & 3;        // 0..3  (16 cols each)
    const int q0 = blockIdx.x * 128;
    const int h  = blockIdx.y;
    const int b  = blockIdx.z;

    __nv_bfloat16* sQh = (__nv_bfloat16*)(smw + SQH);
    __nv_bfloat16* sQl = (__nv_bfloat16*)(smw + SQL);
    __nv_bfloat16* sKh = (__nv_bfloat16*)(smw + SKH);
    __nv_bfloat16* sKl = (__nv_bfloat16*)(smw + SKL);
    __nv_bfloat16* sVh = (__nv_bfloat16*)(smw + SVH);
    __nv_bfloat16* sVl = (__nv_bfloat16*)(smw + SVL);
    float* sS  = (float*)(smw + SSS);
    __nv_bfloat16* sPh = (__nv_bfloat16*)(smw + SPH);
    __nv_bfloat16* sPl = (__nv_bfloat16*)(smw + SPL);
    float* sM  = (float*)(smw + SMM);
    float* sL  = (float*)(smw + SLL);
    float* sA  = (float*)(smw + SAL);

    const size_t hoff = (size_t)h * HDIM;
    const size_t brow = (size_t)(b * SEQ);

    // KV loader: 64 rows x 8 x16B chunks per array; 1 chunk/thread/array
    const int kr = tid >> 3, kc = (tid & 7) * 16;

    auto issueK = [&](int t) {
        const size_t g = (brow + t*64 + kr) * EMB + hoff;
        __pipeline_memcpy_async(smw + SKH + kr*144 + kc, (const char*)Kh + g*2 + kc, 16);
        __pipeline_memcpy_async(smw + SKL + kr*144 + kc, (const char*)Kl + g*2 + kc, 16);
        __pipeline_commit();
    };
    auto issueV = [&](int t) {
        const size_t g = (brow + t*64 + kr) * EMB + hoff;
        __pipeline_memcpy_async(smw + SVH + kr*144 + kc, (const char*)Vh + g*2 + kc, 16);
        __pipeline_memcpy_async(smw + SVL + kr*144 + kc, (const char*)Vl + g*2 + kc, 16);
        __pipeline_commit();
    };

    issueK(0);

    // Q load (plain): 128 rows x 8 chunks per array, 2 chunks/thread/array
    #pragma unroll
    for (int i = 0; i < 2; i++) {
        const int idx = tid + i * 512;
        const int r = idx >> 3, c = (idx & 7) * 16;
        const size_t g = (brow + q0 + r) * EMB + hoff;
        *(uint4*)(smw + SQH + r*144 + c) = *(const uint4*)((const char*)Qh + g*2 + c);
        *(uint4*)(smw + SQL + r*144 + c) = *(const uint4*)((const char*)Ql + g*2 + c);
    }

    // Probe: discover per-element row of the 16x16 accumulator fragment
    if (tid < 256) sS[(tid >> 4) * FW_FPITCH + (tid & 15)] = (float)(tid >> 4);
    if (tid < 128) { sM[tid] = -INFINITY; sL[tid] = 0.f; }
    __syncthreads();

    int rowid[8];
    {
        wmma::fragment<wmma::accumulator, 16, 16, 16, float> probe;
        wmma::load_matrix_sync(probe, sS, FW_FPITCH, wmma::mem_row_major);
        #pragma unroll
        for (int e = 0; e < probe.num_elements && e < 8; e++)
            rowid[e] = (int)probe.x[e];
    }

    // O accumulators live in registers for the whole KV loop
    wmma::fragment<wmma::accumulator, 16, 16, 16, float> oc[2];
    wmma::fill_fragment(oc[0], 0.f);
    wmma::fill_fragment(oc[1], 0.f);

    const int srow = tid >> 2;          // softmax row 0..127
    const int ssub = tid & 3;
    const int sc0  = ssub * 16;

    for (int t = 0; t < SEQ/64; t++) {
        __pipeline_wait_prior(0);       // K_t resident
        __syncthreads();
        issueV(t);

        // ---- S = Q K^T (3-pass split): per warp 2 tiles (32 rows x 16 cols)
        #pragma unroll
        for (int mt = 0; mt < 2; mt++) {
            wmma::fragment<wmma::accumulator, 16, 16, 16, float> sc;
            wmma::fill_fragment(sc, 0.f);
            #pragma unroll
            for (int ks = 0; ks < 4; ks++) {
                wmma::fragment<wmma::matrix_a, 16, 16, 16, __nv_bfloat16, wmma::row_major> ah, al;
                const int ro = (warp_m*32 + mt*16) * FW_PITCH + ks*16;
                wmma::load_matrix_sync(ah, sQh + ro, FW_PITCH);
                wmma::load_matrix_sync(al, sQl + ro, FW_PITCH);
                wmma::fragment<wmma::matrix_b, 16, 16, 16, __nv_bfloat16, wmma::col_major> bh, bl;
                const int co = (warp_n*16) * FW_PITCH + ks*16;
                wmma::load_matrix_sync(bh, sKh + co, FW_PITCH);
                wmma::load_matrix_sync(bl, sKl + co, FW_PITCH);
                wmma::mma_sync(sc, ah, bh, sc);
                wmma::mma_sync(sc, ah, bl, sc);
                wmma::mma_sync(sc, al, bh, sc);
            }
            wmma::store_matrix_sync(sS + (warp_m*32 + mt*16)*FW_FPITCH + warp_n*16,
                                    sc, FW_FPITCH, wmma::mem_row_major);
        }
        __syncthreads();

        // ---- online softmax (4 threads/row), write P hi/lo + alpha
        {
            float mt_ = -INFINITY;
            #pragma unroll
            for (int j = 0; j < 16; j++)
                mt_ = fmaxf(mt_, sS[srow*FW_FPITCH + sc0 + j]);
            mt_ = fmaxf(mt_, __shfl_xor_sync(0xffffffffu, mt_, 1, 4));
            mt_ = fmaxf(mt_, __shfl_xor_sync(0xffffffffu, mt_, 2, 4));

            const float m_old = sM[srow];
            const float m_new = fmaxf(m_old, mt_);
            const float alpha = __expf(m_old - m_new);

            float ls = 0.f;
            #pragma unroll
            for (int j = 0; j < 16; j++) {
                const float p = __expf(sS[srow*FW_FPITCH + sc0 + j] - m_new);
                ls += p;
                const __nv_bfloat16 ph = __float2bfloat16(p);
                sPh[srow*FW_PITCH + sc0 + j] = ph;
                sPl[srow*FW_PITCH + sc0 + j] = __float2bfloat16(p - __bfloat162float(ph));
            }
            ls += __shfl_xor_sync(0xffffffffu, ls, 1, 4);
            ls += __shfl_xor_sync(0xffffffffu, ls, 2, 4);
            if (ssub == 0) {
                sM[srow] = m_new;
                sL[srow] = sL[srow] * alpha + ls;
                sA[srow] = alpha;
            }
        }
        __syncthreads();

        // ---- rescale O in registers by per-row alpha
        #pragma unroll
        for (int mt = 0; mt < 2; mt++) {
            const int base = warp_m*32 + mt*16;
            #pragma unroll
            for (int e = 0; e < 8; e++)
                oc[mt].x[e] *= sA[base + rowid[e]];
        }

        __pipeline_wait_prior(0);       // V_t resident
        __syncthreads();
        if (t + 1 < SEQ/64) issueK(t + 1);

        // ---- O += P V (3-pass split), accumulate in registers
        #pragma unroll
        for (int mt = 0; mt < 2; mt++) {
            #pragma unroll
            for (int ks = 0; ks < 4; ks++) {
                wmma::fragment<wmma::matrix_a, 16, 16, 16, __nv_bfloat16, wmma::row_major> ph, pl;
                const int ro = (warp_m*32 + mt*16) * FW_PITCH + ks*16;
                wmma::load_matrix_sync(ph, sPh + ro, FW_PITCH);
                wmma::load_matrix_sync(pl, sPl + ro, FW_PITCH);
                wmma::fragment<wmma::matrix_b, 16, 16, 16, __nv_bfloat16, wmma::row_major> vh, vl;
                const int vo = (ks*16) * FW_PITCH + warp_n*16;
                wmma::load_matrix_sync(vh, sVh + vo, FW_PITCH);
                wmma::load_matrix_sync(vl, sVl + vo, FW_PITCH);
                wmma::mma_sync(oc[mt], ph, vh, oc[mt]);
                wmma::mma_sync(oc[mt], ph, vl, oc[mt]);
                wmma::mma_sync(oc[mt], pl, vh, oc[mt]);
            }
        }
        // next-iteration top sync protects sP/sV/sS reuse
    }

    // ---- epilogue: stage O to smem, normalize, split, store
    __syncthreads();
    #pragma unroll
    for (int mt = 0; mt < 2; mt++)
        wmma::store_matrix_sync(sS + (warp_m*32 + mt*16)*FW_FPITCH + warp_n*16,
                                oc[mt], FW_FPITCH, wmma::mem_row_major);
    __syncthreads();

    {
        const float inv = 1.0f / sL[srow];
        const size_t o = (brow + q0 + srow) * EMB + hoff + sc0;
        #pragma unroll
        for (int j = 0; j < 16; j += 2) {
            float v0 = sS[srow*FW_FPITCH + sc0 + j]     * inv;
            float v1 = sS[srow*FW_FPITCH + sc0 + j + 1] * inv;
            __nv_bfloat162 hp, lp;
            hp.x = __float2bfloat16(v0);
            hp.y = __float2bfloat16(v1);
            lp.x = __float2bfloat16(v0 - __bfloat162float(hp.x));
            lp.y = __float2bfloat16(v1 - __bfloat162float(hp.y));
            *(__nv_bfloat162*)&Oh[o + j] = hp;
            *(__nv_bfloat162*)&Ol[o + j] = lp;
        }
    }
}

// ---------------------------------------------------------------------------
extern "C" void kernel_launch(void* const* d_in, const int* in_sizes, int n_in,
                              void* d_out, int out_size)
{
    const float* x  = (const float*)d_in[0];
    const float* Wq = (const float*)d_in[1];
    const float* bq = (const float*)d_in[2];
    const float* Wk = (const float*)d_in[3];
    const float* bk = (const float*)d_in[4];
    const float* Wv = (const float*)d_in[5];
    const float* bv = (const float*)d_in[6];
    const float* Wo = (const float*)d_in[7];
    float* out = (float*)d_out;

    __nv_bfloat16 *qh, *ql, *kh, *kl, *vh, *vl, *xh, *xl, *wh, *wl;
    cudaGetSymbolAddress((void**)&qh, g_qh);
    cudaGetSymbolAddress((void**)&ql, g_ql);
    cudaGetSymbolAddress((void**)&kh, g_kh);
    cudaGetSymbolAddress((void**)&kl, g_kl);
    cudaGetSymbolAddress((void**)&vh, g_vh);
    cudaGetSymbolAddress((void**)&vl, g_vl);
    cudaGetSymbolAddress((void**)&xh, g_xh);
    cudaGetSymbolAddress((void**)&xl, g_xl);
    cudaGetSymbolAddress((void**)&wh, g_wh);
    cudaGetSymbolAddress((void**)&wl, g_wl);

    cudaFuncSetAttribute(gemm_wmma,
                         cudaFuncAttributeMaxDynamicSharedMemorySize, GEMM_SMEM);
    cudaFuncSetAttribute(flash_wmma,
                         cudaFuncAttributeMaxDynamicSharedMemorySize, FW_SMEM);

    const int WSZ = EMB * EMB;
    const int xn4 = MROWS * EMB / 4;
    const int wn4 = WSZ / 4;

    split_kernel<<<(xn4 + 255) / 256, 256>>>(x, xh, xl, xn4);
    split_kernel<<<(wn4 + 255) / 256, 256>>>(Wq, wh + 0*WSZ, wl + 0*WSZ, wn4);
    split_kernel<<<(wn4 + 255) / 256, 256>>>(Wk, wh + 1*WSZ, wl + 1*WSZ, wn4);
    split_kernel<<<(wn4 + 255) / 256, 256>>>(Wv, wh + 2*WSZ, wl + 2*WSZ, wn4);
    split_kernel<<<(wn4 + 255) / 256, 256>>>(Wo, wh + 3*WSZ, wl + 3*WSZ, wn4);

    dim3 gg(EMB / 128, MROWS / 128);   // (8, 64)
    gemm_wmma<<<gg, 256, GEMM_SMEM>>>(xh, xl, wh + 0*WSZ, wl + 0*WSZ, bq,
                                      nullptr, qh, ql, 0.125f, EMB);
    gemm_wmma<<<gg, 256, GEMM_SMEM>>>(xh, xl, wh + 1*WSZ, wl + 1*WSZ, bk,
                                      nullptr, kh, kl, 1.0f, EMB);
    gemm_wmma<<<gg, 256, GEMM_SMEM>>>(xh, xl, wh + 2*WSZ, wl + 2*WSZ, bv,
                                      nullptr, vh, vl, 1.0f, EMB);

    dim3 fg(SEQ / 128, HEADS, BATCH);  // (16, 16, 4)
    flash_wmma<<<fg, 512, FW_SMEM>>>(qh, ql, kh, kl, vh, vl, xh, xl);

    gemm_wmma<<<gg, 256, GEMM_SMEM>>>(xh, xl, wh + 3*WSZ, wl + 3*WSZ, nullptr,
                                      out, nullptr, nullptr, 1.0f, EMB);
}

// round 10
// speedup vs baseline: 1.8408x; 1.0119x over previous
#include <cuda_runtime.h>
#include <cuda_bf16.h>
#include <cuda_pipeline.h>
#include <mma.h>
#include <math.h>
#include <stdint.h>

using namespace nvcuda;

// Problem constants
#define BATCH 4
#define SEQ   2048
#define EMB   1024
#define HEADS 16
#define HDIM  64
#define MROWS (BATCH*SEQ)   // 8192

// ---------------------------------------------------------------------------
// Scratch (device globals)
// ---------------------------------------------------------------------------
__device__ __nv_bfloat16 g_qh[MROWS*EMB], g_ql[MROWS*EMB];
__device__ __nv_bfloat16 g_kh[MROWS*EMB], g_kl[MROWS*EMB];
__device__ __nv_bfloat16 g_vh[MROWS*EMB], g_vl[MROWS*EMB];
__device__ __nv_bfloat16 g_xh[MROWS*EMB], g_xl[MROWS*EMB];
__device__ __nv_bfloat16 g_wh[4*EMB*EMB], g_wl[4*EMB*EMB];

// ---------------------------------------------------------------------------
// Split fp32 -> (bf16 hi, bf16 lo)
// ---------------------------------------------------------------------------
__global__ __launch_bounds__(256)
void split_kernel(const float* __restrict__ src,
                  __nv_bfloat16* __restrict__ hi,
                  __nv_bfloat16* __restrict__ lo, int n4)
{
    int i = blockIdx.x * blockDim.x + threadIdx.x;
    if (i >= n4) return;
    float4 v = ((const float4*)src)[i];
    __nv_bfloat16 h0 = __float2bfloat16(v.x);
    __nv_bfloat16 h1 = __float2bfloat16(v.y);
    __nv_bfloat16 h2 = __float2bfloat16(v.z);
    __nv_bfloat16 h3 = __float2bfloat16(v.w);
    __nv_bfloat16 l0 = __float2bfloat16(v.x - __bfloat162float(h0));
    __nv_bfloat16 l1 = __float2bfloat16(v.y - __bfloat162float(h1));
    __nv_bfloat16 l2 = __float2bfloat16(v.z - __bfloat162float(h2));
    __nv_bfloat16 l3 = __float2bfloat16(v.w - __bfloat162float(h3));
    __nv_bfloat162* hp = (__nv_bfloat162*)hi;
    __nv_bfloat162* lp = (__nv_bfloat162*)lo;
    __nv_bfloat162 a; a.x = h0; a.y = h1;
    __nv_bfloat162 b; b.x = h2; b.y = h3;
    __nv_bfloat162 c; c.x = l0; c.y = l1;
    __nv_bfloat162 d; d.x = l2; d.y = l3;
    hp[i*2+0] = a; hp[i*2+1] = b;
    lp[i*2+0] = c; lp[i*2+1] = d;
}

// ---------------------------------------------------------------------------
// WMMA split-bf16 GEMM, 3-stage cp.async pipeline.
// ---------------------------------------------------------------------------
#define NCHUNKS   (EMB/32)
#define PITCH_E   48
#define TILE_SB   (128*PITCH_E*2)     // 12288
#define STAGE_SB  (4*TILE_SB)         // 49152
#define GEMM_SMEM (3*STAGE_SB)        // 147456

__global__ __launch_bounds__(256)
void gemm_wmma(const __nv_bfloat16* __restrict__ Ah, const __nv_bfloat16* __restrict__ Al,
               const __nv_bfloat16* __restrict__ Bh, const __nv_bfloat16* __restrict__ Bl,
               const float* __restrict__ bias,
               float* __restrict__ Cf,
               __nv_bfloat16* __restrict__ outH, __nv_bfloat16* __restrict__ outL,
               float scale, int Nn)
{
    extern __shared__ char smc[];
    const int tid  = threadIdx.x;
    const int wid  = tid >> 5;
    const int warp_m = wid >> 2;
    const int warp_n = wid & 3;
    const int bx = blockIdx.x;
    const int by = blockIdx.y;

    const char* ahg = (const char*)Ah + (size_t)(by*128) * 2048;
    const char* alg = (const char*)Al + (size_t)(by*128) * 2048;
    const char* bhg = (const char*)Bh + (size_t)(bx*128) * 2048;
    const char* blg = (const char*)Bl + (size_t)(bx*128) * 2048;

    int lrow[2], lcb[2];
    #pragma unroll
    for (int i = 0; i < 2; i++) {
        int idx = tid + i * 256;
        lrow[i] = idx >> 2;
        lcb[i]  = (idx & 3) * 16;
    }

    auto load_chunk = [&](int c, int stage) {
        char* st = smc + stage * STAGE_SB;
        const int ko = c * 64;
        #pragma unroll
        for (int i = 0; i < 2; i++) {
            const int    so = lrow[i] * (PITCH_E*2) + lcb[i];
            const size_t go = (size_t)lrow[i] * 2048 + ko + lcb[i];
            __pipeline_memcpy_async(st + 0*TILE_SB + so, ahg + go, 16);
            __pipeline_memcpy_async(st + 1*TILE_SB + so, alg + go, 16);
            __pipeline_memcpy_async(st + 2*TILE_SB + so, bhg + go, 16);
            __pipeline_memcpy_async(st + 3*TILE_SB + so, blg + go, 16);
        }
        __pipeline_commit();
    };

    wmma::fragment<wmma::accumulator, 16, 16, 16, float> acc[4][2];
    #pragma unroll
    for (int mt = 0; mt < 4; mt++)
        #pragma unroll
        for (int nt = 0; nt < 2; nt++)
            wmma::fill_fragment(acc[mt][nt], 0.0f);

    load_chunk(0, 0);
    load_chunk(1, 1);

    for (int c = 0; c < NCHUNKS; c++) {
        if (c + 2 < NCHUNKS) {
            load_chunk(c + 2, (c + 2) % 3);
            __pipeline_wait_prior(2);
        } else if (c + 1 < NCHUNKS) {
            __pipeline_wait_prior(1);
        } else {
            __pipeline_wait_prior(0);
        }
        __syncthreads();

        char* st = smc + (c % 3) * STAGE_SB;
        const __nv_bfloat16* ahs = (const __nv_bfloat16*)(st + 0*TILE_SB);
        const __nv_bfloat16* als = (const __nv_bfloat16*)(st + 1*TILE_SB);
        const __nv_bfloat16* bhs = (const __nv_bfloat16*)(st + 2*TILE_SB);
        const __nv_bfloat16* bls = (const __nv_bfloat16*)(st + 3*TILE_SB);

        #pragma unroll
        for (int ks = 0; ks < 2; ks++) {
            const int ke = ks * 16;

            wmma::fragment<wmma::matrix_a, 16, 16, 16, __nv_bfloat16, wmma::row_major> fah[4], fal[4];
            #pragma unroll
            for (int mt = 0; mt < 4; mt++) {
                const int ro = (warp_m*64 + mt*16) * PITCH_E + ke;
                wmma::load_matrix_sync(fah[mt], ahs + ro, PITCH_E);
                wmma::load_matrix_sync(fal[mt], als + ro, PITCH_E);
            }
            wmma::fragment<wmma::matrix_b, 16, 16, 16, __nv_bfloat16, wmma::col_major> fbh[2], fbl[2];
            #pragma unroll
            for (int nt = 0; nt < 2; nt++) {
                const int ro = (warp_n*32 + nt*16) * PITCH_E + ke;
                wmma::load_matrix_sync(fbh[nt], bhs + ro, PITCH_E);
                wmma::load_matrix_sync(fbl[nt], bls + ro, PITCH_E);
            }

            #pragma unroll
            for (int mt = 0; mt < 4; mt++)
                #pragma unroll
                for (int nt = 0; nt < 2; nt++) {
                    wmma::mma_sync(acc[mt][nt], fah[mt], fbh[nt], acc[mt][nt]);
                    wmma::mma_sync(acc[mt][nt], fah[mt], fbl[nt], acc[mt][nt]);
                    wmma::mma_sync(acc[mt][nt], fal[mt], fbh[nt], acc[mt][nt]);
                }
        }
        __syncthreads();
    }

    float* Cs = (float*)smc;
    #pragma unroll
    for (int mt = 0; mt < 4; mt++)
        #pragma unroll
        for (int nt = 0; nt < 2; nt++)
            wmma::store_matrix_sync(Cs + (warp_m*64 + mt*16)*132 + warp_n*32 + nt*16,
                                    acc[mt][nt], 132, wmma::mem_row_major);
    __syncthreads();

    const int r  = tid >> 1;
    const int c0 = (tid & 1) * 64;
    if (outH == nullptr) {
        #pragma unroll
        for (int j = 0; j < 16; j++) {
            const int col = c0 + j * 4;
            float4 v = *(float4*)&Cs[r*132 + col];
            if (bias) {
                const float4 bv = *(const float4*)&bias[bx*128 + col];
                v.x += bv.x; v.y += bv.y; v.z += bv.z; v.w += bv.w;
            }
            *(float4*)&Cf[(size_t)(by*128 + r) * Nn + bx*128 + col] = v;
        }
    } else {
        #pragma unroll
        for (int j = 0; j < 16; j++) {
            const int col = c0 + j * 4;
            float4 v = *(float4*)&Cs[r*132 + col];
            if (bias) {
                const float4 bv = *(const float4*)&bias[bx*128 + col];
                v.x += bv.x; v.y += bv.y; v.z += bv.z; v.w += bv.w;
            }
            v.x *= scale; v.y *= scale; v.z *= scale; v.w *= scale;
            __nv_bfloat16 h0 = __float2bfloat16(v.x), h1 = __float2bfloat16(v.y);
            __nv_bfloat16 h2 = __float2bfloat16(v.z), h3 = __float2bfloat16(v.w);
            __nv_bfloat162 hp0; hp0.x = h0; hp0.y = h1;
            __nv_bfloat162 hp1; hp1.x = h2; hp1.y = h3;
            __nv_bfloat162 lp0, lp1;
            lp0.x = __float2bfloat16(v.x - __bfloat162float(h0));
            lp0.y = __float2bfloat16(v.y - __bfloat162float(h1));
            lp1.x = __float2bfloat16(v.z - __bfloat162float(h2));
            lp1.y = __float2bfloat16(v.w - __bfloat162float(h3));
            const size_t o = (size_t)(by*128 + r) * Nn + bx*128 + col;
            *(__nv_bfloat162*)&outH[o]     = hp0;
            *(__nv_bfloat162*)&outH[o + 2] = hp1;
            *(__nv_bfloat162*)&outL[o]     = lp0;
            *(__nv_bfloat162*)&outL[o + 2] = lp1;
        }
    }
}

// ---------------------------------------------------------------------------
// WMMA flash v3: 128 q-rows per CTA, 512 threads, 3 syncs per KV tile,
// K(t+1) prefetch overlaps softmax+PV; V(t) load overlaps S-mma.
// O in registers (probe-derived row ids for alpha rescale).
// ---------------------------------------------------------------------------
#define FW_PITCH  72
#define FW_FPITCH 68
#define SQH 0                 // 128x144
#define SQL 18432
#define SKH 36864             // 64x144
#define SKL 46080
#define SVH 55296
#define SVL 64512
#define SSS 73728             // 128x68 fp32 = 34816
#define SPH 108544            // 128x144 bf16
#define SPL 126976
#define SMM 145408
#define SLL 145920
#define SAL 146432
#define FW_SMEM 146944

__global__ __launch_bounds__(512)
void flash_wmma(const __nv_bfloat16* __restrict__ Qh, const __nv_bfloat16* __restrict__ Ql,
                const __nv_bfloat16* __restrict__ Kh, const __nv_bfloat16* __restrict__ Kl,
                const __nv_bfloat16* __restrict__ Vh, const __nv_bfloat16* __restrict__ Vl,
                __nv_bfloat16* __restrict__ Oh, __nv_bfloat16* __restrict__ Ol)
{
    extern __shared__ char smw[];
    const int tid  = threadIdx.x;
    const int wid  = tid >> 5;
    const int warp_m = wid >> 2;       // 0..3
    const int warp_n = wid & 3;        // 0..3
    const int q0 = blockIdx.x * 128;
    const int h  = blockIdx.y;
    const int b  = blockIdx.z;

    __nv_bfloat16* sQh = (__nv_bfloat16*)(smw + SQH);
    __nv_bfloat16* sQl = (__nv_bfloat16*)(smw + SQL);
    __nv_bfloat16* sKh = (__nv_bfloat16*)(smw + SKH);
    __nv_bfloat16* sKl = (__nv_bfloat16*)(smw + SKL);
    __nv_bfloat16* sVh = (__nv_bfloat16*)(smw + SVH);
    __nv_bfloat16* sVl = (__nv_bfloat16*)(smw + SVL);
    float* sS  = (float*)(smw + SSS);
    __nv_bfloat16* sPh = (__nv_bfloat16*)(smw + SPH);
    __nv_bfloat16* sPl = (__nv_bfloat16*)(smw + SPL);
    float* sM  = (float*)(smw + SMM);
    float* sL  = (float*)(smw + SLL);
    float* sA  = (float*)(smw + SAL);

    const size_t hoff = (size_t)h * HDIM;
    const size_t brow = (size_t)(b * SEQ);

    const int kr = tid >> 3, kc = (tid & 7) * 16;

    auto issueK = [&](int t) {
        const size_t g = (brow + t*64 + kr) * EMB + hoff;
        __pipeline_memcpy_async(smw + SKH + kr*144 + kc, (const char*)Kh + g*2 + kc, 16);
        __pipeline_memcpy_async(smw + SKL + kr*144 + kc, (const char*)Kl + g*2 + kc, 16);
        __pipeline_commit();
    };
    auto issueV = [&](int t) {
        const size_t g = (brow + t*64 + kr) * EMB + hoff;
        __pipeline_memcpy_async(smw + SVH + kr*144 + kc, (const char*)Vh + g*2 + kc, 16);
        __pipeline_memcpy_async(smw + SVL + kr*144 + kc, (const char*)Vl + g*2 + kc, 16);
        __pipeline_commit();
    };

    issueK(0);

    // Q load (plain)
    #pragma unroll
    for (int i = 0; i < 2; i++) {
        const int idx = tid + i * 512;
        const int r = idx >> 3, c = (idx & 7) * 16;
        const size_t g = (brow + q0 + r) * EMB + hoff;
        *(uint4*)(smw + SQH + r*144 + c) = *(const uint4*)((const char*)Qh + g*2 + c);
        *(uint4*)(smw + SQL + r*144 + c) = *(const uint4*)((const char*)Ql + g*2 + c);
    }

    // Probe: per-element row index of the accumulator fragment layout
    if (tid < 256) sS[(tid >> 4) * FW_FPITCH + (tid & 15)] = (float)(tid >> 4);
    if (tid < 128) { sM[tid] = -INFINITY; sL[tid] = 0.f; }
    __syncthreads();

    int rowid[8];
    {
        wmma::fragment<wmma::accumulator, 16, 16, 16, float> probe;
        wmma::load_matrix_sync(probe, sS, FW_FPITCH, wmma::mem_row_major);
        #pragma unroll
        for (int e = 0; e < probe.num_elements && e < 8; e++)
            rowid[e] = (int)probe.x[e];
    }

    wmma::fragment<wmma::accumulator, 16, 16, 16, float> oc[2];
    wmma::fill_fragment(oc[0], 0.f);
    wmma::fill_fragment(oc[1], 0.f);

    const int srow = tid >> 2;
    const int ssub = tid & 3;
    const int sc0  = ssub * 16;

    const int NT = SEQ / 64;
    for (int t = 0; t < NT; t++) {
        __pipeline_wait_prior(0);       // K(t) resident
        __syncthreads();                // + protects sV/sP/sS reuse
        issueV(t);

        // ---- S = Q K^T (3-pass split)
        #pragma unroll
        for (int mt = 0; mt < 2; mt++) {
            wmma::fragment<wmma::accumulator, 16, 16, 16, float> sc;
            wmma::fill_fragment(sc, 0.f);
            #pragma unroll
            for (int ks = 0; ks < 4; ks++) {
                wmma::fragment<wmma::matrix_a, 16, 16, 16, __nv_bfloat16, wmma::row_major> ah, al;
                const int ro = (warp_m*32 + mt*16) * FW_PITCH + ks*16;
                wmma::load_matrix_sync(ah, sQh + ro, FW_PITCH);
                wmma::load_matrix_sync(al, sQl + ro, FW_PITCH);
                wmma::fragment<wmma::matrix_b, 16, 16, 16, __nv_bfloat16, wmma::col_major> bh, bl;
                const int co = (warp_n*16) * FW_PITCH + ks*16;
                wmma::load_matrix_sync(bh, sKh + co, FW_PITCH);
                wmma::load_matrix_sync(bl, sKl + co, FW_PITCH);
                wmma::mma_sync(sc, ah, bh, sc);
                wmma::mma_sync(sc, ah, bl, sc);
                wmma::mma_sync(sc, al, bh, sc);
            }
            wmma::store_matrix_sync(sS + (warp_m*32 + mt*16)*FW_FPITCH + warp_n*16,
                                    sc, FW_FPITCH, wmma::mem_row_major);
        }
        __syncthreads();                // S visible; sK consumed
        if (t + 1 < NT) issueK(t + 1);  // overlaps softmax + PV

        // ---- online softmax (4 threads/row), write P hi/lo + alpha
        {
            float mt_ = -INFINITY;
            #pragma unroll
            for (int j = 0; j < 16; j++)
                mt_ = fmaxf(mt_, sS[srow*FW_FPITCH + sc0 + j]);
            mt_ = fmaxf(mt_, __shfl_xor_sync(0xffffffffu, mt_, 1, 4));
            mt_ = fmaxf(mt_, __shfl_xor_sync(0xffffffffu, mt_, 2, 4));

            const float m_old = sM[srow];
            const float m_new = fmaxf(m_old, mt_);
            const float alpha = __expf(m_old - m_new);

            float ls = 0.f;
            #pragma unroll
            for (int j = 0; j < 16; j++) {
                const float p = __expf(sS[srow*FW_FPITCH + sc0 + j] - m_new);
                ls += p;
                const __nv_bfloat16 ph = __float2bfloat16(p);
                sPh[srow*FW_PITCH + sc0 + j] = ph;
                sPl[srow*FW_PITCH + sc0 + j] = __float2bfloat16(p - __bfloat162float(ph));
            }
            ls += __shfl_xor_sync(0xffffffffu, ls, 1, 4);
            ls += __shfl_xor_sync(0xffffffffu, ls, 2, 4);
            if (ssub == 0) {
                sM[srow] = m_new;
                sL[srow] = sL[srow] * alpha + ls;
                sA[srow] = alpha;
            }
        }
        if (t + 1 < NT) __pipeline_wait_prior(1);   // V(t) done (K(t+1) in flight)
        else            __pipeline_wait_prior(0);
        __syncthreads();                // P/alpha visible; V resident

        // ---- rescale O in registers
        #pragma unroll
        for (int mt = 0; mt < 2; mt++) {
            const int base = warp_m*32 + mt*16;
            #pragma unroll
            for (int e = 0; e < 8; e++)
                oc[mt].x[e] *= sA[base + rowid[e]];
        }

        // ---- O += P V (3-pass split)
        #pragma unroll
        for (int mt = 0; mt < 2; mt++) {
            #pragma unroll
            for (int ks = 0; ks < 4; ks++) {
                wmma::fragment<wmma::matrix_a, 16, 16, 16, __nv_bfloat16, wmma::row_major> ph, pl;
                const int ro = (warp_m*32 + mt*16) * FW_PITCH + ks*16;
                wmma::load_matrix_sync(ph, sPh + ro, FW_PITCH);
                wmma::load_matrix_sync(pl, sPl + ro, FW_PITCH);
                wmma::fragment<wmma::matrix_b, 16, 16, 16, __nv_bfloat16, wmma::row_major> vh, vl;
                const int vo = (ks*16) * FW_PITCH + warp_n*16;
                wmma::load_matrix_sync(vh, sVh + vo, FW_PITCH);
                wmma::load_matrix_sync(vl, sVl + vo, FW_PITCH);
                wmma::mma_sync(oc[mt], ph, vh, oc[mt]);
                wmma::mma_sync(oc[mt], ph, vl, oc[mt]);
                wmma::mma_sync(oc[mt], pl, vh, oc[mt]);
            }
        }
    }

    // ---- epilogue
    __syncthreads();
    #pragma unroll
    for (int mt = 0; mt < 2; mt++)
        wmma::store_matrix_sync(sS + (warp_m*32 + mt*16)*FW_FPITCH + warp_n*16,
                                oc[mt], FW_FPITCH, wmma::mem_row_major);
    __syncthreads();

    {
        const float inv = 1.0f / sL[srow];
        const size_t o = (brow + q0 + srow) * EMB + hoff + sc0;
        #pragma unroll
        for (int j = 0; j < 16; j += 2) {
            float v0 = sS[srow*FW_FPITCH + sc0 + j]     * inv;
            float v1 = sS[srow*FW_FPITCH + sc0 + j + 1] * inv;
            __nv_bfloat162 hp, lp;
            hp.x = __float2bfloat16(v0);
            hp.y = __float2bfloat16(v1);
            lp.x = __float2bfloat16(v0 - __bfloat162float(hp.x));
            lp.y = __float2bfloat16(v1 - __bfloat162float(hp.y));
            *(__nv_bfloat162*)&Oh[o + j] = hp;
            *(__nv_bfloat162*)&Ol[o + j] = lp;
        }
    }
}

// ---------------------------------------------------------------------------
extern "C" void kernel_launch(void* const* d_in, const int* in_sizes, int n_in,
                              void* d_out, int out_size)
{
    const float* x  = (const float*)d_in[0];
    const float* Wq = (const float*)d_in[1];
    const float* bq = (const float*)d_in[2];
    const float* Wk = (const float*)d_in[3];
    const float* bk = (const float*)d_in[4];
    const float* Wv = (const float*)d_in[5];
    const float* bv = (const float*)d_in[6];
    const float* Wo = (const float*)d_in[7];
    float* out = (float*)d_out;

    __nv_bfloat16 *qh, *ql, *kh, *kl, *vh, *vl, *xh, *xl, *wh, *wl;
    cudaGetSymbolAddress((void**)&qh, g_qh);
    cudaGetSymbolAddress((void**)&ql, g_ql);
    cudaGetSymbolAddress((void**)&kh, g_kh);
    cudaGetSymbolAddress((void**)&kl, g_kl);
    cudaGetSymbolAddress((void**)&vh, g_vh);
    cudaGetSymbolAddress((void**)&vl, g_vl);
    cudaGetSymbolAddress((void**)&xh, g_xh);
    cudaGetSymbolAddress((void**)&xl, g_xl);
    cudaGetSymbolAddress((void**)&wh, g_wh);
    cudaGetSymbolAddress((void**)&wl, g_wl);

    cudaFuncSetAttribute(gemm_wmma,
                         cudaFuncAttributeMaxDynamicSharedMemorySize, GEMM_SMEM);
    cudaFuncSetAttribute(flash_wmma,
                         cudaFuncAttributeMaxDynamicSharedMemorySize, FW_SMEM);

    const int WSZ = EMB * EMB;
    const int xn4 = MROWS * EMB / 4;
    const int wn4 = WSZ / 4;

    split_kernel<<<(xn4 + 255) / 256, 256>>>(x, xh, xl, xn4);
    split_kernel<<<(wn4 + 255) / 256, 256>>>(Wq, wh + 0*WSZ, wl + 0*WSZ, wn4);
    split_kernel<<<(wn4 + 255) / 256, 256>>>(Wk, wh + 1*WSZ, wl + 1*WSZ, wn4);
    split_kernel<<<(wn4 + 255) / 256, 256>>>(Wv, wh + 2*WSZ, wl + 2*WSZ, wn4);
    split_kernel<<<(wn4 + 255) / 256, 256>>>(Wo, wh + 3*WSZ, wl + 3*WSZ, wn4);

    dim3 gg(EMB / 128, MROWS / 128);   // (8, 64)
    gemm_wmma<<<gg, 256, GEMM_SMEM>>>(xh, xl, wh + 0*WSZ, wl + 0*WSZ, bq,
                                      nullptr, qh, ql, 0.125f, EMB);
    gemm_wmma<<<gg, 256, GEMM_SMEM>>>(xh, xl, wh + 1*WSZ, wl + 1*WSZ, bk,
                                      nullptr, kh, kl, 1.0f, EMB);
    gemm_wmma<<<gg, 256, GEMM_SMEM>>>(xh, xl, wh + 2*WSZ, wl + 2*WSZ, bv,
                                      nullptr, vh, vl, 1.0f, EMB);

    dim3 fg(SEQ / 128, HEADS, BATCH);  // (16, 16, 4)
    flash_wmma<<<fg, 512, FW_SMEM>>>(qh, ql, kh, kl, vh, vl, xh, xl);

    gemm_wmma<<<gg, 256, GEMM_SMEM>>>(xh, xl, wh + 3*WSZ, wl + 3*WSZ, nullptr,
                                      out, nullptr, nullptr, 1.0f, EMB);
}

// round 12
// speedup vs baseline: 1.8762x; 1.0192x over previous
#include <cuda_runtime.h>
#include <cuda_bf16.h>
#include <cuda_pipeline.h>
#include <mma.h>
#include <math.h>
#include <stdint.h>

using namespace nvcuda;

// Problem constants
#define BATCH 4
#define SEQ   2048
#define EMB   1024
#define HEADS 16
#define HDIM  64
#define MROWS (BATCH*SEQ)   // 8192

// ---------------------------------------------------------------------------
// Scratch (device globals)
// ---------------------------------------------------------------------------
__device__ __nv_bfloat16 g_qh[MROWS*EMB], g_ql[MROWS*EMB];
__device__ __nv_bfloat16 g_kh[MROWS*EMB], g_kl[MROWS*EMB];
__device__ __nv_bfloat16 g_vh[MROWS*EMB], g_vl[MROWS*EMB];
__device__ __nv_bfloat16 g_xh[MROWS*EMB], g_xl[MROWS*EMB];
__device__ __nv_bfloat16 g_wh[4*EMB*EMB], g_wl[4*EMB*EMB];

// ---------------------------------------------------------------------------
// Split fp32 -> (bf16 hi, bf16 lo)
// ---------------------------------------------------------------------------
__device__ __forceinline__ void split4_store(float4 v, __nv_bfloat162* hp,
                                             __nv_bfloat162* lp, size_t o2)
{
    __nv_bfloat16 h0 = __float2bfloat16(v.x);
    __nv_bfloat16 h1 = __float2bfloat16(v.y);
    __nv_bfloat16 h2 = __float2bfloat16(v.z);
    __nv_bfloat16 h3 = __float2bfloat16(v.w);
    __nv_bfloat162 a; a.x = h0; a.y = h1;
    __nv_bfloat162 b; b.x = h2; b.y = h3;
    __nv_bfloat162 c, d;
    c.x = __float2bfloat16(v.x - __bfloat162float(h0));
    c.y = __float2bfloat16(v.y - __bfloat162float(h1));
    d.x = __float2bfloat16(v.z - __bfloat162float(h2));
    d.y = __float2bfloat16(v.w - __bfloat162float(h3));
    hp[o2+0] = a; hp[o2+1] = b;
    lp[o2+0] = c; lp[o2+1] = d;
}

__global__ __launch_bounds__(256)
void split_kernel(const float* __restrict__ src,
                  __nv_bfloat16* __restrict__ hi,
                  __nv_bfloat16* __restrict__ lo, int n4)
{
    int i = blockIdx.x * blockDim.x + threadIdx.x;
    if (i >= n4) return;
    float4 v = ((const float4*)src)[i];
    split4_store(v, (__nv_bfloat162*)hi, (__nv_bfloat162*)lo, (size_t)i*2);
}

// All 4 weight matrices in ONE launch.
__global__ __launch_bounds__(256)
void split4_kernel(const float* __restrict__ s0, const float* __restrict__ s1,
                   const float* __restrict__ s2, const float* __restrict__ s3,
                   __nv_bfloat16* __restrict__ hi, __nv_bfloat16* __restrict__ lo,
                   int n4each)
{
    int i = blockIdx.x * blockDim.x + threadIdx.x;
    if (i >= 4 * n4each) return;
    int w = i / n4each;
    int j = i - w * n4each;
    const float* src = (w == 0) ? s0 : (w == 1) ? s1 : (w == 2) ? s2 : s3;
    float4 v = ((const float4*)src)[j];
    split4_store(v, (__nv_bfloat162*)hi, (__nv_bfloat162*)lo,
                 ((size_t)w * n4each + j) * 2);
}

// ---------------------------------------------------------------------------
// WMMA split-bf16 GEMM, 2-stage cp.async, pass-outer mma ordering (acc RAW
// chains spaced by 8 independent mmas).
// ---------------------------------------------------------------------------
#define NCHUNKS   (EMB/32)
#define PITCH_E   48
#define TILE_SB   (128*PITCH_E*2)     // 12288
#define STAGE_SB  (4*TILE_SB)         // 49152
#define GEMM_SMEM (2*STAGE_SB)        // 98304

__global__ __launch_bounds__(256)
void gemm_wmma(const __nv_bfloat16* __restrict__ Ah, const __nv_bfloat16* __restrict__ Al,
               const __nv_bfloat16* __restrict__ Bh, const __nv_bfloat16* __restrict__ Bl,
               const float* __restrict__ bias,
               float* __restrict__ Cf,
               __nv_bfloat16* __restrict__ outH, __nv_bfloat16* __restrict__ outL,
               float scale, int Nn)
{
    extern __shared__ char smc[];
    const int tid  = threadIdx.x;
    const int wid  = tid >> 5;
    const int warp_m = wid >> 2;
    const int warp_n = wid & 3;
    const int bx = blockIdx.x;
    const int by = blockIdx.y;

    const char* ahg = (const char*)Ah + (size_t)(by*128) * 2048;
    const char* alg = (const char*)Al + (size_t)(by*128) * 2048;
    const char* bhg = (const char*)Bh + (size_t)(bx*128) * 2048;
    const char* blg = (const char*)Bl + (size_t)(bx*128) * 2048;

    int lrow[2], lcb[2];
    #pragma unroll
    for (int i = 0; i < 2; i++) {
        int idx = tid + i * 256;
        lrow[i] = idx >> 2;
        lcb[i]  = (idx & 3) * 16;
    }

    auto load_chunk = [&](int c, int stage) {
        char* st = smc + stage * STAGE_SB;
        const int ko = c * 64;
        #pragma unroll
        for (int i = 0; i < 2; i++) {
            const int    so = lrow[i] * (PITCH_E*2) + lcb[i];
            const size_t go = (size_t)lrow[i] * 2048 + ko + lcb[i];
            __pipeline_memcpy_async(st + 0*TILE_SB + so, ahg + go, 16);
            __pipeline_memcpy_async(st + 1*TILE_SB + so, alg + go, 16);
            __pipeline_memcpy_async(st + 2*TILE_SB + so, bhg + go, 16);
            __pipeline_memcpy_async(st + 3*TILE_SB + so, blg + go, 16);
        }
        __pipeline_commit();
    };

    wmma::fragment<wmma::accumulator, 16, 16, 16, float> acc[4][2];
    #pragma unroll
    for (int mt = 0; mt < 4; mt++)
        #pragma unroll
        for (int nt = 0; nt < 2; nt++)
            wmma::fill_fragment(acc[mt][nt], 0.0f);

    load_chunk(0, 0);

    for (int c = 0; c < NCHUNKS; c++) {
        if (c + 1 < NCHUNKS) {
            load_chunk(c + 1, (c + 1) & 1);
            __pipeline_wait_prior(1);
        } else {
            __pipeline_wait_prior(0);
        }
        __syncthreads();

        char* st = smc + (c & 1) * STAGE_SB;
        const __nv_bfloat16* ahs = (const __nv_bfloat16*)(st + 0*TILE_SB);
        const __nv_bfloat16* als = (const __nv_bfloat16*)(st + 1*TILE_SB);
        const __nv_bfloat16* bhs = (const __nv_bfloat16*)(st + 2*TILE_SB);
        const __nv_bfloat16* bls = (const __nv_bfloat16*)(st + 3*TILE_SB);

        #pragma unroll
        for (int ks = 0; ks < 2; ks++) {
            const int ke = ks * 16;

            wmma::fragment<wmma::matrix_a, 16, 16, 16, __nv_bfloat16, wmma::row_major> fah[4], fal[4];
            #pragma unroll
            for (int mt = 0; mt < 4; mt++) {
                const int ro = (warp_m*64 + mt*16) * PITCH_E + ke;
                wmma::load_matrix_sync(fah[mt], ahs + ro, PITCH_E);
                wmma::load_matrix_sync(fal[mt], als + ro, PITCH_E);
            }
            wmma::fragment<wmma::matrix_b, 16, 16, 16, __nv_bfloat16, wmma::col_major> fbh[2], fbl[2];
            #pragma unroll
            for (int nt = 0; nt < 2; nt++) {
                const int ro = (warp_n*32 + nt*16) * PITCH_E + ke;
                wmma::load_matrix_sync(fbh[nt], bhs + ro, PITCH_E);
                wmma::load_matrix_sync(fbl[nt], bls + ro, PITCH_E);
            }

            // Pass-outer: same-acc reuse spaced by 8 independent mmas
            #pragma unroll
            for (int mt = 0; mt < 4; mt++)
                #pragma unroll
                for (int nt = 0; nt < 2; nt++)
                    wmma::mma_sync(acc[mt][nt], fah[mt], fbh[nt], acc[mt][nt]);
            #pragma unroll
            for (int mt = 0; mt < 4; mt++)
                #pragma unroll
                for (int nt = 0; nt < 2; nt++)
                    wmma::mma_sync(acc[mt][nt], fah[mt], fbl[nt], acc[mt][nt]);
            #pragma unroll
            for (int mt = 0; mt < 4; mt++)
                #pragma unroll
                for (int nt = 0; nt < 2; nt++)
                    wmma::mma_sync(acc[mt][nt], fal[mt], fbh[nt], acc[mt][nt]);
        }
        __syncthreads();
    }

    float* Cs = (float*)smc;
    #pragma unroll
    for (int mt = 0; mt < 4; mt++)
        #pragma unroll
        for (int nt = 0; nt < 2; nt++)
            wmma::store_matrix_sync(Cs + (warp_m*64 + mt*16)*132 + warp_n*32 + nt*16,
                                    acc[mt][nt], 132, wmma::mem_row_major);
    __syncthreads();

    const int r  = tid >> 1;
    const int c0 = (tid & 1) * 64;
    if (outH == nullptr) {
        #pragma unroll
        for (int j = 0; j < 16; j++) {
            const int col = c0 + j * 4;
            float4 v = *(float4*)&Cs[r*132 + col];
            if (bias) {
                const float4 bv = *(const float4*)&bias[bx*128 + col];
                v.x += bv.x; v.y += bv.y; v.z += bv.z; v.w += bv.w;
            }
            *(float4*)&Cf[(size_t)(by*128 + r) * Nn + bx*128 + col] = v;
        }
    } else {
        #pragma unroll
        for (int j = 0; j < 16; j++) {
            const int col = c0 + j * 4;
            float4 v = *(float4*)&Cs[r*132 + col];
            if (bias) {
                const float4 bv = *(const float4*)&bias[bx*128 + col];
                v.x += bv.x; v.y += bv.y; v.z += bv.z; v.w += bv.w;
            }
            v.x *= scale; v.y *= scale; v.z *= scale; v.w *= scale;
            __nv_bfloat16 h0 = __float2bfloat16(v.x), h1 = __float2bfloat16(v.y);
            __nv_bfloat16 h2 = __float2bfloat16(v.z), h3 = __float2bfloat16(v.w);
            __nv_bfloat162 hp0; hp0.x = h0; hp0.y = h1;
            __nv_bfloat162 hp1; hp1.x = h2; hp1.y = h3;
            __nv_bfloat162 lp0, lp1;
            lp0.x = __float2bfloat16(v.x - __bfloat162float(h0));
            lp0.y = __float2bfloat16(v.y - __bfloat162float(h1));
            lp1.x = __float2bfloat16(v.z - __bfloat162float(h2));
            lp1.y = __float2bfloat16(v.w - __bfloat162float(h3));
            const size_t o = (size_t)(by*128 + r) * Nn + bx*128 + col;
            *(__nv_bfloat162*)&outH[o]     = hp0;
            *(__nv_bfloat162*)&outH[o + 2] = hp1;
            *(__nv_bfloat162*)&outL[o]     = lp0;
            *(__nv_bfloat162*)&outL[o + 2] = lp1;
        }
    }
}

// ---------------------------------------------------------------------------
// WMMA flash v4: per-pass accumulators (sch/scx, oc/ox) + ks-outer ordering
// break the 12-deep mma RAW chains of v3. O (hi+cross) in registers.
// ---------------------------------------------------------------------------
#define FW_PITCH  72
#define FW_FPITCH 68
#define SQH 0                 // 128x144
#define SQL 18432
#define SKH 36864             // 64x144
#define SKL 46080
#define SVH 55296
#define SVL 64512
#define SSS 73728             // 128x68 fp32 = 34816
#define SPH 108544            // 128x144 bf16
#define SPL 126976
#define SMM 145408
#define SLL 145920
#define SAL 146432
#define FW_SMEM 146944

__global__ __launch_bounds__(512)
void flash_wmma(const __nv_bfloat16* __restrict__ Qh, const __nv_bfloat16* __restrict__ Ql,
                const __nv_bfloat16* __restrict__ Kh, const __nv_bfloat16* __restrict__ Kl,
                const __nv_bfloat16* __restrict__ Vh, const __nv_bfloat16* __restrict__ Vl,
                __nv_bfloat16* __restrict__ Oh, __nv_bfloat16* __restrict__ Ol)
{
    extern __shared__ char smw[];
    const int tid  = threadIdx.x;
    const int wid  = tid >> 5;
    const int warp_m = wid >> 2;       // 0..3
    const int warp_n = wid & 3;        // 0..3
    const int q0 = blockIdx.x * 128;
    const int h  = blockIdx.y;
    const int b  = blockIdx.z;

    __nv_bfloat16* sQh = (__nv_bfloat16*)(smw + SQH);
    __nv_bfloat16* sQl = (__nv_bfloat16*)(smw + SQL);
    __nv_bfloat16* sKh = (__nv_bfloat16*)(smw + SKH);
    __nv_bfloat16* sKl = (__nv_bfloat16*)(smw + SKL);
    __nv_bfloat16* sVh = (__nv_bfloat16*)(smw + SVH);
    __nv_bfloat16* sVl = (__nv_bfloat16*)(smw + SVL);
    float* sS  = (float*)(smw + SSS);
    __nv_bfloat16* sPh = (__nv_bfloat16*)(smw + SPH);
    __nv_bfloat16* sPl = (__nv_bfloat16*)(smw + SPL);
    float* sM  = (float*)(smw + SMM);
    float* sL  = (float*)(smw + SLL);
    float* sA  = (float*)(smw + SAL);

    const size_t hoff = (size_t)h * HDIM;
    const size_t brow = (size_t)(b * SEQ);

    const int kr = tid >> 3, kc = (tid & 7) * 16;

    auto issueK = [&](int t) {
        const size_t g = (brow + t*64 + kr) * EMB + hoff;
        __pipeline_memcpy_async(smw + SKH + kr*144 + kc, (const char*)Kh + g*2 + kc, 16);
        __pipeline_memcpy_async(smw + SKL + kr*144 + kc, (const char*)Kl + g*2 + kc, 16);
        __pipeline_commit();
    };
    auto issueV = [&](int t) {
        const size_t g = (brow + t*64 + kr) * EMB + hoff;
        __pipeline_memcpy_async(smw + SVH + kr*144 + kc, (const char*)Vh + g*2 + kc, 16);
        __pipeline_memcpy_async(smw + SVL + kr*144 + kc, (const char*)Vl + g*2 + kc, 16);
        __pipeline_commit();
    };

    issueK(0);

    // Q load (plain)
    #pragma unroll
    for (int i = 0; i < 2; i++) {
        const int idx = tid + i * 512;
        const int r = idx >> 3, c = (idx & 7) * 16;
        const size_t g = (brow + q0 + r) * EMB + hoff;
        *(uint4*)(smw + SQH + r*144 + c) = *(const uint4*)((const char*)Qh + g*2 + c);
        *(uint4*)(smw + SQL + r*144 + c) = *(const uint4*)((const char*)Ql + g*2 + c);
    }

    // Probe: per-element row index of the accumulator fragment layout
    if (tid < 256) sS[(tid >> 4) * FW_FPITCH + (tid & 15)] = (float)(tid >> 4);
    if (tid < 128) { sM[tid] = -INFINITY; sL[tid] = 0.f; }
    __syncthreads();

    int rowid[8];
    {
        wmma::fragment<wmma::accumulator, 16, 16, 16, float> probe;
        wmma::load_matrix_sync(probe, sS, FW_FPITCH, wmma::mem_row_major);
        #pragma unroll
        for (int e = 0; e < probe.num_elements && e < 8; e++)
            rowid[e] = (int)probe.x[e];
    }

    // O accumulators: oc (hi*hi) + ox (cross terms), both persistent
    wmma::fragment<wmma::accumulator, 16, 16, 16, float> oc[2], ox[2];
    wmma::fill_fragment(oc[0], 0.f); wmma::fill_fragment(oc[1], 0.f);
    wmma::fill_fragment(ox[0], 0.f); wmma::fill_fragment(ox[1], 0.f);

    const int srow = tid >> 2;
    const int ssub = tid & 3;
    const int sc0  = ssub * 16;

    const int NT = SEQ / 64;
    for (int t = 0; t < NT; t++) {
        __pipeline_wait_prior(0);       // K(t) resident
        __syncthreads();                // + protects sV/sP/sS reuse
        issueV(t);

        // ---- S = Q K^T, ks-outer, hh-acc + cross-acc per mt
        {
            wmma::fragment<wmma::accumulator, 16, 16, 16, float> sch[2], scx[2];
            wmma::fill_fragment(sch[0], 0.f); wmma::fill_fragment(sch[1], 0.f);
            wmma::fill_fragment(scx[0], 0.f); wmma::fill_fragment(scx[1], 0.f);

            #pragma unroll
            for (int ks = 0; ks < 4; ks++) {
                wmma::fragment<wmma::matrix_a, 16, 16, 16, __nv_bfloat16, wmma::row_major> ah[2], al[2];
                #pragma unroll
                for (int mt = 0; mt < 2; mt++) {
                    const int ro = (warp_m*32 + mt*16) * FW_PITCH + ks*16;
                    wmma::load_matrix_sync(ah[mt], sQh + ro, FW_PITCH);
                    wmma::load_matrix_sync(al[mt], sQl + ro, FW_PITCH);
                }
                wmma::fragment<wmma::matrix_b, 16, 16, 16, __nv_bfloat16, wmma::col_major> bh, bl;
                const int co = (warp_n*16) * FW_PITCH + ks*16;
                wmma::load_matrix_sync(bh, sKh + co, FW_PITCH);
                wmma::load_matrix_sync(bl, sKl + co, FW_PITCH);

                wmma::mma_sync(sch[0], ah[0], bh, sch[0]);
                wmma::mma_sync(sch[1], ah[1], bh, sch[1]);
                wmma::mma_sync(scx[0], ah[0], bl, scx[0]);
                wmma::mma_sync(scx[1], ah[1], bl, scx[1]);
                wmma::mma_sync(scx[0], al[0], bh, scx[0]);
                wmma::mma_sync(scx[1], al[1], bh, scx[1]);
            }
            #pragma unroll
            for (int mt = 0; mt < 2; mt++) {
                #pragma unroll
                for (int e = 0; e < 8; e++) sch[mt].x[e] += scx[mt].x[e];
                wmma::store_matrix_sync(sS + (warp_m*32 + mt*16)*FW_FPITCH + warp_n*16,
                                        sch[mt], FW_FPITCH, wmma::mem_row_major);
            }
        }
        __syncthreads();                // S visible; sK consumed
        if (t + 1 < NT) issueK(t + 1);  // overlaps softmax + PV

        // ---- online softmax (4 threads/row), write P hi/lo + alpha
        {
            float mt_ = -INFINITY;
            #pragma unroll
            for (int j = 0; j < 16; j++)
                mt_ = fmaxf(mt_, sS[srow*FW_FPITCH + sc0 + j]);
            mt_ = fmaxf(mt_, __shfl_xor_sync(0xffffffffu, mt_, 1, 4));
            mt_ = fmaxf(mt_, __shfl_xor_sync(0xffffffffu, mt_, 2, 4));

            const float m_old = sM[srow];
            const float m_new = fmaxf(m_old, mt_);
            const float alpha = __expf(m_old - m_new);

            float ls = 0.f;
            #pragma unroll
            for (int j = 0; j < 16; j++) {
                const float p = __expf(sS[srow*FW_FPITCH + sc0 + j] - m_new);
                ls += p;
                const __nv_bfloat16 ph = __float2bfloat16(p);
                sPh[srow*FW_PITCH + sc0 + j] = ph;
                sPl[srow*FW_PITCH + sc0 + j] = __float2bfloat16(p - __bfloat162float(ph));
            }
            ls += __shfl_xor_sync(0xffffffffu, ls, 1, 4);
            ls += __shfl_xor_sync(0xffffffffu, ls, 2, 4);
            if (ssub == 0) {
                sM[srow] = m_new;
                sL[srow] = sL[srow] * alpha + ls;
                sA[srow] = alpha;
            }
        }
        if (t + 1 < NT) __pipeline_wait_prior(1);   // V(t) done (K(t+1) in flight)
        else            __pipeline_wait_prior(0);
        __syncthreads();                // P/alpha visible; V resident

        // ---- rescale O (both accumulators) in registers
        #pragma unroll
        for (int mt = 0; mt < 2; mt++) {
            const int base = warp_m*32 + mt*16;
            #pragma unroll
            for (int e = 0; e < 8; e++) {
                const float a = sA[base + rowid[e]];
                oc[mt].x[e] *= a;
                ox[mt].x[e] *= a;
            }
        }

        // ---- O += P V, ks-outer, split accumulators
        #pragma unroll
        for (int ks = 0; ks < 4; ks++) {
            wmma::fragment<wmma::matrix_a, 16, 16, 16, __nv_bfloat16, wmma::row_major> ph[2], pl[2];
            #pragma unroll
            for (int mt = 0; mt < 2; mt++) {
                const int ro = (warp_m*32 + mt*16) * FW_PITCH + ks*16;
                wmma::load_matrix_sync(ph[mt], sPh + ro, FW_PITCH);
                wmma::load_matrix_sync(pl[mt], sPl + ro, FW_PITCH);
            }
            wmma::fragment<wmma::matrix_b, 16, 16, 16, __nv_bfloat16, wmma::row_major> vh, vl;
            const int vo = (ks*16) * FW_PITCH + warp_n*16;
            wmma::load_matrix_sync(vh, sVh + vo, FW_PITCH);
            wmma::load_matrix_sync(vl, sVl + vo, FW_PITCH);

            wmma::mma_sync(oc[0], ph[0], vh, oc[0]);
            wmma::mma_sync(oc[1], ph[1], vh, oc[1]);
            wmma::mma_sync(ox[0], ph[0], vl, ox[0]);
            wmma::mma_sync(ox[1], ph[1], vl, ox[1]);
            wmma::mma_sync(ox[0], pl[0], vh, ox[0]);
            wmma::mma_sync(ox[1], pl[1], vh, ox[1]);
        }
    }

    // ---- epilogue: fold ox into oc, stage, normalize, split, store
    __syncthreads();
    #pragma unroll
    for (int mt = 0; mt < 2; mt++) {
        #pragma unroll
        for (int e = 0; e < 8; e++) oc[mt].x[e] += ox[mt].x[e];
        wmma::store_matrix_sync(sS + (warp_m*32 + mt*16)*FW_FPITCH + warp_n*16,
                                oc[mt], FW_FPITCH, wmma::mem_row_major);
    }
    __syncthreads();

    {
        const float inv = 1.0f / sL[srow];
        const size_t o = (brow + q0 + srow) * EMB + hoff + sc0;
        #pragma unroll
        for (int j = 0; j < 16; j += 2) {
            float v0 = sS[srow*FW_FPITCH + sc0 + j]     * inv;
            float v1 = sS[srow*FW_FPITCH + sc0 + j + 1] * inv;
            __nv_bfloat162 hp, lp;
            hp.x = __float2bfloat16(v0);
            hp.y = __float2bfloat16(v1);
            lp.x = __float2bfloat16(v0 - __bfloat162float(hp.x));
            lp.y = __float2bfloat16(v1 - __bfloat162float(hp.y));
            *(__nv_bfloat162*)&Oh[o + j] = hp;
            *(__nv_bfloat162*)&Ol[o + j] = lp;
        }
    }
}

// ---------------------------------------------------------------------------
extern "C" void kernel_launch(void* const* d_in, const int* in_sizes, int n_in,
                              void* d_out, int out_size)
{
    const float* x  = (const float*)d_in[0];
    const float* Wq = (const float*)d_in[1];
    const float* bq = (const float*)d_in[2];
    const float* Wk = (const float*)d_in[3];
    const float* bk = (const float*)d_in[4];
    const float* Wv = (const float*)d_in[5];
    const float* bv = (const float*)d_in[6];
    const float* Wo = (const float*)d_in[7];
    float* out = (float*)d_out;

    __nv_bfloat16 *qh, *ql, *kh, *kl, *vh, *vl, *xh, *xl, *wh, *wl;
    cudaGetSymbolAddress((void**)&qh, g_qh);
    cudaGetSymbolAddress((void**)&ql, g_ql);
    cudaGetSymbolAddress((void**)&kh, g_kh);
    cudaGetSymbolAddress((void**)&kl, g_kl);
    cudaGetSymbolAddress((void**)&vh, g_vh);
    cudaGetSymbolAddress((void**)&vl, g_vl);
    cudaGetSymbolAddress((void**)&xh, g_xh);
    cudaGetSymbolAddress((void**)&xl, g_xl);
    cudaGetSymbolAddress((void**)&wh, g_wh);
    cudaGetSymbolAddress((void**)&wl, g_wl);

    cudaFuncSetAttribute(gemm_wmma,
                         cudaFuncAttributeMaxDynamicSharedMemorySize, GEMM_SMEM);
    cudaFuncSetAttribute(flash_wmma,
                         cudaFuncAttributeMaxDynamicSharedMemorySize, FW_SMEM);

    const int WSZ = EMB * EMB;
    const int xn4 = MROWS * EMB / 4;
    const int wn4 = WSZ / 4;

    split_kernel <<<(xn4 + 255) / 256, 256>>>(x, xh, xl, xn4);
    split4_kernel<<<(4*wn4 + 255) / 256, 256>>>(Wq, Wk, Wv, Wo, wh, wl, wn4);

    dim3 gg(EMB / 128, MROWS / 128);   // (8, 64)
    gemm_wmma<<<gg, 256, GEMM_SMEM>>>(xh, xl, wh + 0*WSZ, wl + 0*WSZ, bq,
                                      nullptr, qh, ql, 0.125f, EMB);
    gemm_wmma<<<gg, 256, GEMM_SMEM>>>(xh, xl, wh + 1*WSZ, wl + 1*WSZ, bk,
                                      nullptr, kh, kl, 1.0f, EMB);
    gemm_wmma<<<gg, 256, GEMM_SMEM>>>(xh, xl, wh + 2*WSZ, wl + 2*WSZ, bv,
                                      nullptr, vh, vl, 1.0f, EMB);

    dim3 fg(SEQ / 128, HEADS, BATCH);  // (16, 16, 4)
    flash_wmma<<<fg, 512, FW_SMEM>>>(qh, ql, kh, kl, vh, vl, xh, xl);

    gemm_wmma<<<gg, 256, GEMM_SMEM>>>(xh, xl, wh + 3*WSZ, wl + 3*WSZ, nullptr,
                                      out, nullptr, nullptr, 1.0f, EMB);
}